// round 3
// baseline (speedup 1.0000x reference)
#include <cuda_runtime.h>
#include <cuda_bf16.h>
#include <cstdint>
#include <cstddef>

#define IN_DIM 1024
#define HID    2048
#define OUTD   10
#define NEX    3
#define NT     10
#define BATCH  4096

// ---------------- static device scratch (no runtime allocation) ----------------
__device__ __align__(256) __nv_bfloat16 g_x_hi[(size_t)BATCH * IN_DIM];
__device__ __align__(256) __nv_bfloat16 g_x_lo[(size_t)BATCH * IN_DIM];
__device__ __align__(256) __nv_bfloat16 g_w0_hi[(size_t)HID * IN_DIM];
__device__ __align__(256) __nv_bfloat16 g_w0_lo[(size_t)HID * IN_DIM];
__device__ __align__(256) __nv_bfloat16 g_w_hi[(size_t)NEX * HID * HID];
__device__ __align__(256) __nv_bfloat16 g_w_lo[(size_t)NEX * HID * HID];
__device__ __align__(256) float         g_bias[HID + NEX * HID];      // b0 | b1 b2 b3
__device__ __align__(256) float         g_hw[(size_t)NT * OUTD * HID];
__device__ __align__(256) float         g_hb[NT * OUTD];
__device__ __align__(256) __nv_bfloat16 g_h_hi[2][(size_t)BATCH * HID];
__device__ __align__(256) __nv_bfloat16 g_h_lo[2][(size_t)BATCH * HID];
__device__ int g_task_is64;   // 1 if task buffer is int64, 0 if int32

// ---------------- task dtype detection ----------------
// Reads the task buffer as int32[BATCH] (safe for both int32[BATCH] and
// int64[BATCH] underlying layouts). For little-endian int64 with values in
// [0,10), every odd int32 word is zero. For int32, odd words are real task
// ids (all-zero has probability ~10^-2048).
__global__ void detect_task_kernel(const int* __restrict__ t32) {
    __shared__ int any;
    if (threadIdx.x == 0) any = 0;
    __syncthreads();
    int local = 0;
    for (int i = 1 + 2 * threadIdx.x; i < BATCH; i += 2 * blockDim.x) local |= t32[i];
    if (local) atomicOr(&any, 1);
    __syncthreads();
    if (threadIdx.x == 0) g_task_is64 = (any == 0) ? 1 : 0;
}

// ---------------- elementwise generation kernels ----------------

__global__ void split_x_kernel(const float* __restrict__ x, int n) {
    int i = blockIdx.x * blockDim.x + threadIdx.x;
    if (i >= n) return;
    float v = x[i];
    __nv_bfloat16 h = __float2bfloat16(v);
    g_x_hi[i] = h;
    g_x_lo[i] = __float2bfloat16(v - __bfloat162float(h));
}

__global__ void gen_split_w_kernel(const float* __restrict__ mu,
                                   const float* __restrict__ ls,
                                   const float* __restrict__ eps,
                                   int which, int n) {
    int i = blockIdx.x * blockDim.x + threadIdx.x;
    if (i >= n) return;
    float w = fmaf(expf(ls[i]), eps[i], mu[i]);
    __nv_bfloat16 h = __float2bfloat16(w);
    __nv_bfloat16 l = __float2bfloat16(w - __bfloat162float(h));
    if (which == 0) { g_w0_hi[i] = h; g_w0_lo[i] = l; }
    else            { g_w_hi[i]  = h; g_w_lo[i]  = l; }
}

__global__ void gen_f32_kernel(const float* __restrict__ mu,
                               const float* __restrict__ ls,
                               const float* __restrict__ eps,
                               int which, int n) {
    int i = blockIdx.x * blockDim.x + threadIdx.x;
    if (i >= n) return;
    float w = fmaf(expf(ls[i]), eps[i], mu[i]);
    float* dst = (which == 0) ? g_bias
               : (which == 1) ? (g_bias + HID)
               : (which == 2) ? g_hw
               :                g_hb;
    dst[i] = w;
}

// ---------------- split-bf16 GEMM (C = A * W^T + bias, ReLU, re-split) ----------------
// A: [M,K] row-major (hi/lo bf16), W: [N,K] row-major (hi/lo bf16)
// Tile: BM=128, BN=128, BK=32. 256 threads = 8 warps (4 along M x 2 along N),
// warp tile 32x64 -> 2 m16 tiles x 8 n8 tiles, 3 MMAs per tile (hi*hi, hi*lo, lo*hi).

#define BM   128
#define BN   128
#define BKT  32
#define PADK 40   // padded smem row stride (elements); 80B, 16B-aligned

__device__ __forceinline__ void ldsm4(uint32_t d[4], uint32_t addr) {
    asm volatile("ldmatrix.sync.aligned.m8n8.x4.shared.b16 {%0,%1,%2,%3}, [%4];"
                 : "=r"(d[0]), "=r"(d[1]), "=r"(d[2]), "=r"(d[3]) : "r"(addr));
}

__device__ __forceinline__ void mma_bf16(float c[4], const uint32_t a[4], const uint32_t b[2]) {
    asm volatile("mma.sync.aligned.m16n8k16.row.col.f32.bf16.bf16.f32 "
                 "{%0,%1,%2,%3}, {%4,%5,%6,%7}, {%8,%9}, {%0,%1,%2,%3};"
                 : "+f"(c[0]), "+f"(c[1]), "+f"(c[2]), "+f"(c[3])
                 : "r"(a[0]), "r"(a[1]), "r"(a[2]), "r"(a[3]), "r"(b[0]), "r"(b[1]));
}

__global__ __launch_bounds__(256) void gemm_split_kernel(int layer, int a_sel, int out_sel) {
    const __nv_bfloat16 *Ahi, *Alo, *Whi, *Wlo;
    const float* bias;
    int K;
    if (layer == 0) {
        Ahi = g_x_hi; Alo = g_x_lo;
        Whi = g_w0_hi; Wlo = g_w0_lo;
        bias = g_bias; K = IN_DIM;
    } else {
        Ahi = g_h_hi[a_sel]; Alo = g_h_lo[a_sel];
        Whi = g_w_hi + (size_t)(layer - 1) * HID * HID;
        Wlo = g_w_lo + (size_t)(layer - 1) * HID * HID;
        bias = g_bias + layer * HID; K = HID;
    }
    __nv_bfloat16* Chi = g_h_hi[out_sel];
    __nv_bfloat16* Clo = g_h_lo[out_sel];

    __shared__ __align__(128) __nv_bfloat16 sAhi[BM * PADK];
    __shared__ __align__(128) __nv_bfloat16 sAlo[BM * PADK];
    __shared__ __align__(128) __nv_bfloat16 sBhi[BN * PADK];
    __shared__ __align__(128) __nv_bfloat16 sBlo[BN * PADK];

    const uint32_t sAhiB = (uint32_t)__cvta_generic_to_shared(sAhi);
    const uint32_t sAloB = (uint32_t)__cvta_generic_to_shared(sAlo);
    const uint32_t sBhiB = (uint32_t)__cvta_generic_to_shared(sBhi);
    const uint32_t sBloB = (uint32_t)__cvta_generic_to_shared(sBlo);

    const int tid  = threadIdx.x;
    const int warp = tid >> 5;
    const int lane = tid & 31;
    const int m0 = blockIdx.y * BM;
    const int n0 = blockIdx.x * BN;
    const int wm0 = (warp & 3) * 32;   // warp row offset in tile
    const int wn0 = (warp >> 2) * 64;  // warp col offset in tile

    const int lrow  = tid >> 1;
    const int cbase = (tid & 1) * 2;

    float acc[2][8][4];
#pragma unroll
    for (int mt = 0; mt < 2; mt++)
#pragma unroll
        for (int nt = 0; nt < 8; nt++)
#pragma unroll
            for (int i = 0; i < 4; i++) acc[mt][nt][i] = 0.f;

    uint4 regs[8];
    {
        const uint4* pa_hi = reinterpret_cast<const uint4*>(Ahi + (size_t)(m0 + lrow) * K);
        const uint4* pa_lo = reinterpret_cast<const uint4*>(Alo + (size_t)(m0 + lrow) * K);
        const uint4* pb_hi = reinterpret_cast<const uint4*>(Whi + (size_t)(n0 + lrow) * K);
        const uint4* pb_lo = reinterpret_cast<const uint4*>(Wlo + (size_t)(n0 + lrow) * K);
        regs[0] = pa_hi[cbase]; regs[1] = pa_hi[cbase + 1];
        regs[2] = pa_lo[cbase]; regs[3] = pa_lo[cbase + 1];
        regs[4] = pb_hi[cbase]; regs[5] = pb_hi[cbase + 1];
        regs[6] = pb_lo[cbase]; regs[7] = pb_lo[cbase + 1];
    }
    {
        uint4* s;
        s = reinterpret_cast<uint4*>(&sAhi[lrow * PADK + cbase * 8]); s[0] = regs[0]; s[1] = regs[1];
        s = reinterpret_cast<uint4*>(&sAlo[lrow * PADK + cbase * 8]); s[0] = regs[2]; s[1] = regs[3];
        s = reinterpret_cast<uint4*>(&sBhi[lrow * PADK + cbase * 8]); s[0] = regs[4]; s[1] = regs[5];
        s = reinterpret_cast<uint4*>(&sBlo[lrow * PADK + cbase * 8]); s[0] = regs[6]; s[1] = regs[7];
    }
    __syncthreads();

    for (int k0 = 0; k0 < K; k0 += BKT) {
        const bool has_next = (k0 + BKT) < K;
        uint4 nregs[8];
        if (has_next) {
            const int kn = k0 + BKT;
            const uint4* pa_hi = reinterpret_cast<const uint4*>(Ahi + (size_t)(m0 + lrow) * K + kn);
            const uint4* pa_lo = reinterpret_cast<const uint4*>(Alo + (size_t)(m0 + lrow) * K + kn);
            const uint4* pb_hi = reinterpret_cast<const uint4*>(Whi + (size_t)(n0 + lrow) * K + kn);
            const uint4* pb_lo = reinterpret_cast<const uint4*>(Wlo + (size_t)(n0 + lrow) * K + kn);
            nregs[0] = pa_hi[cbase]; nregs[1] = pa_hi[cbase + 1];
            nregs[2] = pa_lo[cbase]; nregs[3] = pa_lo[cbase + 1];
            nregs[4] = pb_hi[cbase]; nregs[5] = pb_hi[cbase + 1];
            nregs[6] = pb_lo[cbase]; nregs[7] = pb_lo[cbase + 1];
        }

#pragma unroll
        for (int kk = 0; kk < BKT; kk += 16) {
            uint32_t ahi[2][4], alo[2][4];
            const int rA  = lane & 15;
            const int chA = (kk >> 3) + (lane >> 4);
#pragma unroll
            for (int mt = 0; mt < 2; mt++) {
                uint32_t off = (uint32_t)(((wm0 + mt * 16 + rA) * PADK + chA * 8) * 2);
                ldsm4(ahi[mt], sAhiB + off);
                ldsm4(alo[mt], sAloB + off);
            }
            uint32_t bhi[8][2], blo[8][2];
            const int rB  = (lane & 7) + ((lane >> 4) << 3);
            const int chB = (kk >> 3) + ((lane >> 3) & 1);
#pragma unroll
            for (int np = 0; np < 4; np++) {
                uint32_t off = (uint32_t)(((wn0 + np * 16 + rB) * PADK + chB * 8) * 2);
                uint32_t d[4];
                ldsm4(d, sBhiB + off);
                bhi[np * 2][0] = d[0]; bhi[np * 2][1] = d[1];
                bhi[np * 2 + 1][0] = d[2]; bhi[np * 2 + 1][1] = d[3];
                ldsm4(d, sBloB + off);
                blo[np * 2][0] = d[0]; blo[np * 2][1] = d[1];
                blo[np * 2 + 1][0] = d[2]; blo[np * 2 + 1][1] = d[3];
            }
#pragma unroll
            for (int mt = 0; mt < 2; mt++)
#pragma unroll
                for (int nt = 0; nt < 8; nt++) {
                    mma_bf16(acc[mt][nt], ahi[mt], bhi[nt]);
                    mma_bf16(acc[mt][nt], ahi[mt], blo[nt]);
                    mma_bf16(acc[mt][nt], alo[mt], bhi[nt]);
                }
        }
        __syncthreads();
        if (has_next) {
            uint4* s;
            s = reinterpret_cast<uint4*>(&sAhi[lrow * PADK + cbase * 8]); s[0] = nregs[0]; s[1] = nregs[1];
            s = reinterpret_cast<uint4*>(&sAlo[lrow * PADK + cbase * 8]); s[0] = nregs[2]; s[1] = nregs[3];
            s = reinterpret_cast<uint4*>(&sBhi[lrow * PADK + cbase * 8]); s[0] = nregs[4]; s[1] = nregs[5];
            s = reinterpret_cast<uint4*>(&sBlo[lrow * PADK + cbase * 8]); s[0] = nregs[6]; s[1] = nregs[7];
            __syncthreads();
        }
    }

    // ---- epilogue: bias + relu + split to bf16 hi/lo ----
    const int gid  = lane >> 2;
    const int tid4 = lane & 3;
#pragma unroll
    for (int nt = 0; nt < 8; nt++) {
        const int col = n0 + wn0 + nt * 8 + tid4 * 2;
        const float bz0 = bias[col];
        const float bz1 = bias[col + 1];
#pragma unroll
        for (int mt = 0; mt < 2; mt++) {
            const int rowm = m0 + wm0 + mt * 16 + gid;
            const float* a = acc[mt][nt];
            {
                float v0 = fmaxf(a[0] + bz0, 0.f);
                float v1 = fmaxf(a[1] + bz1, 0.f);
                __nv_bfloat16 h0 = __float2bfloat16(v0);
                __nv_bfloat16 h1 = __float2bfloat16(v1);
                __nv_bfloat16 l0 = __float2bfloat16(v0 - __bfloat162float(h0));
                __nv_bfloat16 l1 = __float2bfloat16(v1 - __bfloat162float(h1));
                *reinterpret_cast<__nv_bfloat162*>(Chi + (size_t)rowm * HID + col) =
                    __halves2bfloat162(h0, h1);
                *reinterpret_cast<__nv_bfloat162*>(Clo + (size_t)rowm * HID + col) =
                    __halves2bfloat162(l0, l1);
            }
            {
                float v0 = fmaxf(a[2] + bz0, 0.f);
                float v1 = fmaxf(a[3] + bz1, 0.f);
                __nv_bfloat16 h0 = __float2bfloat16(v0);
                __nv_bfloat16 h1 = __float2bfloat16(v1);
                __nv_bfloat16 l0 = __float2bfloat16(v0 - __bfloat162float(h0));
                __nv_bfloat16 l1 = __float2bfloat16(v1 - __bfloat162float(h1));
                *reinterpret_cast<__nv_bfloat162*>(Chi + (size_t)(rowm + 8) * HID + col) =
                    __halves2bfloat162(h0, h1);
                *reinterpret_cast<__nv_bfloat162*>(Clo + (size_t)(rowm + 8) * HID + col) =
                    __halves2bfloat162(l0, l1);
            }
        }
    }
}

// ---------------- task-gathered multihead ----------------
__global__ __launch_bounds__(128) void head_kernel(int h_sel,
                                                   const int* __restrict__ task32,
                                                   float* __restrict__ out) {
    const int b = blockIdx.x;
    // dtype-robust task read (see detect_task_kernel) + defensive clamp
    int t = g_task_is64 ? task32[2 * b] : task32[b];
    t = min(max(t, 0), NT - 1);

    const __nv_bfloat16* hhi = g_h_hi[h_sel] + (size_t)b * HID;
    const __nv_bfloat16* hlo = g_h_lo[h_sel] + (size_t)b * HID;
    const float* hw = g_hw + (size_t)t * OUTD * HID;

    float acc[OUTD];
#pragma unroll
    for (int o = 0; o < OUTD; o++) acc[o] = 0.f;

    for (int k = threadIdx.x; k < HID; k += blockDim.x) {
        float hv = __bfloat162float(hhi[k]) + __bfloat162float(hlo[k]);
#pragma unroll
        for (int o = 0; o < OUTD; o++) acc[o] = fmaf(hv, hw[(size_t)o * HID + k], acc[o]);
    }

    const int warp = threadIdx.x >> 5;
    const int lane = threadIdx.x & 31;
    __shared__ float red[4][OUTD];
#pragma unroll
    for (int o = 0; o < OUTD; o++) {
        float v = acc[o];
#pragma unroll
        for (int s = 16; s > 0; s >>= 1) v += __shfl_xor_sync(0xffffffffu, v, s);
        if (lane == 0) red[warp][o] = v;
    }
    __syncthreads();
    if (threadIdx.x < OUTD) {
        float s = red[0][threadIdx.x] + red[1][threadIdx.x] +
                  red[2][threadIdx.x] + red[3][threadIdx.x] +
                  g_hb[t * OUTD + threadIdx.x];
        out[(size_t)b * OUTD + threadIdx.x] = s;
    }
}

// ---------------- launch ----------------
extern "C" void kernel_launch(void* const* d_in, const int* in_sizes, int n_in,
                              void* d_out, int out_size) {
    (void)in_sizes; (void)n_in; (void)out_size;
    const float* x      = (const float*)d_in[0];
    const float* mu_w0  = (const float*)d_in[1];
    const float* ls_w0  = (const float*)d_in[2];
    const float* mu_b0  = (const float*)d_in[3];
    const float* ls_b0  = (const float*)d_in[4];
    const float* mu_w   = (const float*)d_in[5];
    const float* ls_w   = (const float*)d_in[6];
    const float* mu_b   = (const float*)d_in[7];
    const float* ls_b   = (const float*)d_in[8];
    const float* mu_hw  = (const float*)d_in[9];
    const float* ls_hw  = (const float*)d_in[10];
    const float* mu_hb  = (const float*)d_in[11];
    const float* ls_hb  = (const float*)d_in[12];
    const float* eps_w0 = (const float*)d_in[13];
    const float* eps_b0 = (const float*)d_in[14];
    const float* eps_w  = (const float*)d_in[15];
    const float* eps_b  = (const float*)d_in[16];
    const float* eps_hw = (const float*)d_in[17];
    const float* eps_hb = (const float*)d_in[18];
    const int* task32   = (const int*)d_in[19];
    float* out = (float*)d_out;

    detect_task_kernel<<<1, 256>>>(task32);

    int n;
    n = BATCH * IN_DIM;
    split_x_kernel<<<(n + 255) / 256, 256>>>(x, n);
    n = HID * IN_DIM;
    gen_split_w_kernel<<<(n + 255) / 256, 256>>>(mu_w0, ls_w0, eps_w0, 0, n);
    n = NEX * HID * HID;
    gen_split_w_kernel<<<(n + 255) / 256, 256>>>(mu_w, ls_w, eps_w, 1, n);
    n = HID;
    gen_f32_kernel<<<(n + 255) / 256, 256>>>(mu_b0, ls_b0, eps_b0, 0, n);
    n = NEX * HID;
    gen_f32_kernel<<<(n + 255) / 256, 256>>>(mu_b, ls_b, eps_b, 1, n);
    n = NT * OUTD * HID;
    gen_f32_kernel<<<(n + 255) / 256, 256>>>(mu_hw, ls_hw, eps_hw, 2, n);
    n = NT * OUTD;
    gen_f32_kernel<<<(n + 255) / 256, 256>>>(mu_hb, ls_hb, eps_hb, 3, n);

    dim3 grid(HID / BN, BATCH / BM);
    gemm_split_kernel<<<grid, 256>>>(0, 0, 0);  // x -> h[0]   (K=1024, W0)
    gemm_split_kernel<<<grid, 256>>>(1, 0, 1);  // h[0] -> h[1]
    gemm_split_kernel<<<grid, 256>>>(2, 1, 0);  // h[1] -> h[0]
    gemm_split_kernel<<<grid, 256>>>(3, 0, 1);  // h[0] -> h[1]
    head_kernel<<<BATCH, 128>>>(1, task32, out);
}

// round 6
// speedup vs baseline: 1.1184x; 1.1184x over previous
#include <cuda_runtime.h>
#include <cuda_bf16.h>
#include <cstdint>
#include <cstddef>

#define IN_DIM 1024
#define HID    2048
#define OUTD   10
#define NEX    3
#define NT     10
#define BATCH  4096

// GEMM tiling
#define BM      256
#define BN      128
#define BK      32
#define GTHREADS 512
#define SA_HI   0u
#define SA_LO   20480u    // 256*80
#define SB_HI   40960u
#define SB_LO   51200u    // +128*80
#define STAGE   61440u
#define NSTAGE  3
#define DYN_SMEM (NSTAGE * STAGE)   // 184320 B

// ---------------- static device scratch ----------------
__device__ __align__(256) __nv_bfloat16 g_x_hi[(size_t)BATCH * IN_DIM];
__device__ __align__(256) __nv_bfloat16 g_x_lo[(size_t)BATCH * IN_DIM];
__device__ __align__(256) __nv_bfloat16 g_w0_hi[(size_t)HID * IN_DIM];
__device__ __align__(256) __nv_bfloat16 g_w0_lo[(size_t)HID * IN_DIM];
__device__ __align__(256) __nv_bfloat16 g_w_hi[(size_t)NEX * HID * HID];
__device__ __align__(256) __nv_bfloat16 g_w_lo[(size_t)NEX * HID * HID];
__device__ __align__(256) float         g_bias[HID + NEX * HID];
__device__ __align__(256) float         g_hw[(size_t)NT * OUTD * HID];
__device__ __align__(256) float         g_hb[NT * OUTD];
__device__ __align__(256) __nv_bfloat16 g_h_hi[2][(size_t)BATCH * HID];
__device__ __align__(256) __nv_bfloat16 g_h_lo[2][(size_t)BATCH * HID];
__device__ int g_task_is64;

// ---------------- task dtype detection (validated) ----------------
__global__ void detect_task_kernel(const int* __restrict__ t32) {
    __shared__ int any;
    if (threadIdx.x == 0) any = 0;
    __syncthreads();
    int local = 0;
    for (int i = 1 + 2 * threadIdx.x; i < BATCH; i += 2 * blockDim.x) local |= t32[i];
    if (local) atomicOr(&any, 1);
    __syncthreads();
    if (threadIdx.x == 0) g_task_is64 = (any == 0) ? 1 : 0;
}

// ---------------- elementwise generation (float4-vectorized) ----------------
__device__ __forceinline__ void split1(float v, unsigned short& h, unsigned short& l) {
    __nv_bfloat16 hb = __float2bfloat16(v);
    __nv_bfloat16 lb = __float2bfloat16(v - __bfloat162float(hb));
    h = __bfloat16_as_ushort(hb);
    l = __bfloat16_as_ushort(lb);
}

__global__ void split_x4_kernel(const float4* __restrict__ x, int n4) {
    int i = blockIdx.x * blockDim.x + threadIdx.x;
    if (i >= n4) return;
    float4 v = x[i];
    unsigned short h0, h1, h2, h3, l0, l1, l2, l3;
    split1(v.x, h0, l0); split1(v.y, h1, l1); split1(v.z, h2, l2); split1(v.w, h3, l3);
    uint2 H, L;
    H.x = (uint32_t)h0 | ((uint32_t)h1 << 16); H.y = (uint32_t)h2 | ((uint32_t)h3 << 16);
    L.x = (uint32_t)l0 | ((uint32_t)l1 << 16); L.y = (uint32_t)l2 | ((uint32_t)l3 << 16);
    reinterpret_cast<uint2*>(g_x_hi)[i] = H;
    reinterpret_cast<uint2*>(g_x_lo)[i] = L;
}

__global__ void gen_split_w4_kernel(const float4* __restrict__ mu,
                                    const float4* __restrict__ ls,
                                    const float4* __restrict__ eps,
                                    int which, int n4) {
    int i = blockIdx.x * blockDim.x + threadIdx.x;
    if (i >= n4) return;
    float4 m = mu[i], l = ls[i], e = eps[i];
    float w0 = fmaf(expf(l.x), e.x, m.x);
    float w1 = fmaf(expf(l.y), e.y, m.y);
    float w2 = fmaf(expf(l.z), e.z, m.z);
    float w3 = fmaf(expf(l.w), e.w, m.w);
    unsigned short h0, h1, h2, h3, l0, l1, l2, l3;
    split1(w0, h0, l0); split1(w1, h1, l1); split1(w2, h2, l2); split1(w3, h3, l3);
    uint2 H, L;
    H.x = (uint32_t)h0 | ((uint32_t)h1 << 16); H.y = (uint32_t)h2 | ((uint32_t)h3 << 16);
    L.x = (uint32_t)l0 | ((uint32_t)l1 << 16); L.y = (uint32_t)l2 | ((uint32_t)l3 << 16);
    if (which == 0) {
        reinterpret_cast<uint2*>(g_w0_hi)[i] = H;
        reinterpret_cast<uint2*>(g_w0_lo)[i] = L;
    } else {
        reinterpret_cast<uint2*>(g_w_hi)[i] = H;
        reinterpret_cast<uint2*>(g_w_lo)[i] = L;
    }
}

__global__ void gen_f32_kernel(const float* __restrict__ mu,
                               const float* __restrict__ ls,
                               const float* __restrict__ eps,
                               int which, int n) {
    int i = blockIdx.x * blockDim.x + threadIdx.x;
    if (i >= n) return;
    float w = fmaf(expf(ls[i]), eps[i], mu[i]);
    float* dst = (which == 0) ? g_bias
               : (which == 1) ? (g_bias + HID)
               : (which == 2) ? g_hw
               :                g_hb;
    dst[i] = w;
}

// ---------------- HMMA GEMM primitives (round-3 validated maps) ----------------
__device__ __forceinline__ void ldsm4(uint32_t d[4], uint32_t addr) {
    asm volatile("ldmatrix.sync.aligned.m8n8.x4.shared.b16 {%0,%1,%2,%3}, [%4];"
                 : "=r"(d[0]), "=r"(d[1]), "=r"(d[2]), "=r"(d[3]) : "r"(addr));
}

__device__ __forceinline__ void mma_bf16(float c[4], const uint32_t a[4], const uint32_t b[2]) {
    asm volatile("mma.sync.aligned.m16n8k16.row.col.f32.bf16.bf16.f32 "
                 "{%0,%1,%2,%3}, {%4,%5,%6,%7}, {%8,%9}, {%0,%1,%2,%3};"
                 : "+f"(c[0]), "+f"(c[1]), "+f"(c[2]), "+f"(c[3])
                 : "r"(a[0]), "r"(a[1]), "r"(a[2]), "r"(a[3]), "r"(b[0]), "r"(b[1]));
}

__device__ __forceinline__ void cp16(uint32_t dst, const void* src) {
    asm volatile("cp.async.cg.shared.global [%0], [%1], 16;" :: "r"(dst), "l"(src) : "memory");
}

// load one BK=32 chunk into stage `sb` (all 4 arrays), 6 cp16 per thread
__device__ __forceinline__ void load_chunk(
    uint32_t sb,
    const __nv_bfloat16* __restrict__ Ahi, const __nv_bfloat16* __restrict__ Alo,
    const __nv_bfloat16* __restrict__ Whi, const __nv_bfloat16* __restrict__ Wlo,
    int K, int m0, int n0, int kc, int tid)
{
#pragma unroll
    for (int j = 0; j < 2; j++) {        // A: 256 rows x 4 16B-chunks = 1024 lines
        int idx = tid + j * GTHREADS;
        int row = idx >> 2, ch = idx & 3;
        uint32_t dst = sb + (uint32_t)(row * 80 + ch * 16);
        size_t g = (size_t)(m0 + row) * K + kc + ch * 8;
        cp16(dst + SA_HI, Ahi + g);
        cp16(dst + SA_LO, Alo + g);
    }
    {                                    // B: 128 rows x 4 chunks = 512 lines
        int row = tid >> 2, ch = tid & 3;
        uint32_t dst = sb + (uint32_t)(row * 80 + ch * 16);
        size_t g = (size_t)(n0 + row) * K + kc + ch * 8;
        cp16(dst + SB_HI, Whi + g);
        cp16(dst + SB_LO, Wlo + g);
    }
}

// ---------------- split-bf16 GEMM: C = relu(A*W^T + bias), re-split ----------------
__global__ __launch_bounds__(GTHREADS, 1) void gemm_split_kernel(int layer, int a_sel, int out_sel) {
    const __nv_bfloat16 *Ahi, *Alo, *Whi, *Wlo;
    const float* bias;
    int K;
    if (layer == 0) {
        Ahi = g_x_hi; Alo = g_x_lo; Whi = g_w0_hi; Wlo = g_w0_lo;
        bias = g_bias; K = IN_DIM;
    } else {
        Ahi = g_h_hi[a_sel]; Alo = g_h_lo[a_sel];
        Whi = g_w_hi + (size_t)(layer - 1) * HID * HID;
        Wlo = g_w_lo + (size_t)(layer - 1) * HID * HID;
        bias = g_bias + layer * HID; K = HID;
    }
    __nv_bfloat16* Chi = g_h_hi[out_sel];
    __nv_bfloat16* Clo = g_h_lo[out_sel];
    const int NC = K / BK;

    extern __shared__ __align__(128) uint8_t dyn[];
    const uint32_t sbase = (uint32_t)__cvta_generic_to_shared(dyn);

    const int tid  = threadIdx.x;
    const int warp = tid >> 5;
    const int lane = tid & 31;
    const int m0 = blockIdx.y * BM;
    const int n0 = blockIdx.x * BN;
    const int wm0 = (warp & 3) * 64;    // 4 warps along M, tile 64
    const int wn0 = (warp >> 2) * 32;   // 4 warps along N, tile 32

    float acc[4][4][4];
#pragma unroll
    for (int mt = 0; mt < 4; mt++)
#pragma unroll
        for (int nt = 0; nt < 4; nt++)
#pragma unroll
            for (int i = 0; i < 4; i++) acc[mt][nt][i] = 0.f;

    // prologue: chunks 0,1 -> stages 0,1
    load_chunk(sbase,         Ahi, Alo, Whi, Wlo, K, m0, n0, 0,  tid);
    asm volatile("cp.async.commit_group;" ::: "memory");
    load_chunk(sbase + STAGE, Ahi, Alo, Whi, Wlo, K, m0, n0, BK, tid);
    asm volatile("cp.async.commit_group;" ::: "memory");

    for (int i = 0; i < NC; i++) {
        if (i + 1 < NC) asm volatile("cp.async.wait_group 1;" ::: "memory");
        else            asm volatile("cp.async.wait_group 0;" ::: "memory");
        __syncthreads();
        if (i + 2 < NC) {
            load_chunk(sbase + (uint32_t)((i + 2) % NSTAGE) * STAGE,
                       Ahi, Alo, Whi, Wlo, K, m0, n0, (i + 2) * BK, tid);
            asm volatile("cp.async.commit_group;" ::: "memory");
        }

        const uint32_t sb = sbase + (uint32_t)(i % NSTAGE) * STAGE;
#pragma unroll
        for (int kk = 0; kk < BK; kk += 16) {
            // A fragments: 4 m16 tiles, hi+lo
            uint32_t ahi[4][4], alo[4][4];
            const int rA  = lane & 15;
            const int chA = (kk >> 3) + (lane >> 4);
#pragma unroll
            for (int mt = 0; mt < 4; mt++) {
                uint32_t off = (uint32_t)((wm0 + mt * 16 + rA) * 80 + chA * 16);
                ldsm4(ahi[mt], sb + SA_HI + off);
                ldsm4(alo[mt], sb + SA_LO + off);
            }
            // B: two x4 loads cover 4 n8 tiles; process in pairs to limit liveness
            const int rB  = (lane & 7) + ((lane >> 4) << 3);
            const int chB = (kk >> 3) + ((lane >> 3) & 1);
#pragma unroll
            for (int np = 0; np < 2; np++) {
                uint32_t off = (uint32_t)((wn0 + np * 16 + rB) * 80 + chB * 16);
                uint32_t bh[4], bl[4];
                ldsm4(bh, sb + SB_HI + off);
                ldsm4(bl, sb + SB_LO + off);
#pragma unroll
                for (int sub = 0; sub < 2; sub++) {
                    const int nt = np * 2 + sub;
                    const uint32_t bhi2[2] = { bh[sub * 2], bh[sub * 2 + 1] };
                    const uint32_t blo2[2] = { bl[sub * 2], bl[sub * 2 + 1] };
#pragma unroll
                    for (int mt = 0; mt < 4; mt++) {
                        mma_bf16(acc[mt][nt], ahi[mt], bhi2);
                        mma_bf16(acc[mt][nt], ahi[mt], blo2);
                        mma_bf16(acc[mt][nt], alo[mt], bhi2);
                    }
                }
            }
        }
    }

    // ---- epilogue: bias + relu + split to bf16 hi/lo ----
    const int gid  = lane >> 2;
    const int tid4 = lane & 3;
#pragma unroll
    for (int nt = 0; nt < 4; nt++) {
        const int col = n0 + wn0 + nt * 8 + tid4 * 2;
        const float bz0 = bias[col];
        const float bz1 = bias[col + 1];
#pragma unroll
        for (int mt = 0; mt < 4; mt++) {
            const int rowm = m0 + wm0 + mt * 16 + gid;
            const float* a = acc[mt][nt];
            {
                float v0 = fmaxf(a[0] + bz0, 0.f);
                float v1 = fmaxf(a[1] + bz1, 0.f);
                __nv_bfloat16 h0 = __float2bfloat16(v0);
                __nv_bfloat16 h1 = __float2bfloat16(v1);
                __nv_bfloat16 l0 = __float2bfloat16(v0 - __bfloat162float(h0));
                __nv_bfloat16 l1 = __float2bfloat16(v1 - __bfloat162float(h1));
                *reinterpret_cast<__nv_bfloat162*>(Chi + (size_t)rowm * HID + col) =
                    __halves2bfloat162(h0, h1);
                *reinterpret_cast<__nv_bfloat162*>(Clo + (size_t)rowm * HID + col) =
                    __halves2bfloat162(l0, l1);
            }
            {
                float v0 = fmaxf(a[2] + bz0, 0.f);
                float v1 = fmaxf(a[3] + bz1, 0.f);
                __nv_bfloat16 h0 = __float2bfloat16(v0);
                __nv_bfloat16 h1 = __float2bfloat16(v1);
                __nv_bfloat16 l0 = __float2bfloat16(v0 - __bfloat162float(h0));
                __nv_bfloat16 l1 = __float2bfloat16(v1 - __bfloat162float(h1));
                *reinterpret_cast<__nv_bfloat162*>(Chi + (size_t)(rowm + 8) * HID + col) =
                    __halves2bfloat162(h0, h1);
                *reinterpret_cast<__nv_bfloat162*>(Clo + (size_t)(rowm + 8) * HID + col) =
                    __halves2bfloat162(l0, l1);
            }
        }
    }
}

// ---------------- task-gathered multihead ----------------
__global__ __launch_bounds__(128) void head_kernel(int h_sel,
                                                   const int* __restrict__ task32,
                                                   float* __restrict__ out) {
    const int b = blockIdx.x;
    int t = g_task_is64 ? task32[2 * b] : task32[b];
    t = min(max(t, 0), NT - 1);

    const __nv_bfloat16* hhi = g_h_hi[h_sel] + (size_t)b * HID;
    const __nv_bfloat16* hlo = g_h_lo[h_sel] + (size_t)b * HID;
    const float* hw = g_hw + (size_t)t * OUTD * HID;

    float acc[OUTD];
#pragma unroll
    for (int o = 0; o < OUTD; o++) acc[o] = 0.f;

    for (int k = threadIdx.x; k < HID; k += blockDim.x) {
        float hv = __bfloat162float(hhi[k]) + __bfloat162float(hlo[k]);
#pragma unroll
        for (int o = 0; o < OUTD; o++) acc[o] = fmaf(hv, hw[(size_t)o * HID + k], acc[o]);
    }

    const int warp = threadIdx.x >> 5;
    const int lane = threadIdx.x & 31;
    __shared__ float red[4][OUTD];
#pragma unroll
    for (int o = 0; o < OUTD; o++) {
        float v = acc[o];
#pragma unroll
        for (int s = 16; s > 0; s >>= 1) v += __shfl_xor_sync(0xffffffffu, v, s);
        if (lane == 0) red[warp][o] = v;
    }
    __syncthreads();
    if (threadIdx.x < OUTD) {
        float s = red[0][threadIdx.x] + red[1][threadIdx.x] +
                  red[2][threadIdx.x] + red[3][threadIdx.x] +
                  g_hb[t * OUTD + threadIdx.x];
        out[(size_t)b * OUTD + threadIdx.x] = s;
    }
}

// ---------------- launch ----------------
extern "C" void kernel_launch(void* const* d_in, const int* in_sizes, int n_in,
                              void* d_out, int out_size) {
    (void)in_sizes; (void)n_in; (void)out_size;
    const float* x      = (const float*)d_in[0];
    const float* mu_w0  = (const float*)d_in[1];
    const float* ls_w0  = (const float*)d_in[2];
    const float* mu_b0  = (const float*)d_in[3];
    const float* ls_b0  = (const float*)d_in[4];
    const float* mu_w   = (const float*)d_in[5];
    const float* ls_w   = (const float*)d_in[6];
    const float* mu_b   = (const float*)d_in[7];
    const float* ls_b   = (const float*)d_in[8];
    const float* mu_hw  = (const float*)d_in[9];
    const float* ls_hw  = (const float*)d_in[10];
    const float* mu_hb  = (const float*)d_in[11];
    const float* ls_hb  = (const float*)d_in[12];
    const float* eps_w0 = (const float*)d_in[13];
    const float* eps_b0 = (const float*)d_in[14];
    const float* eps_w  = (const float*)d_in[15];
    const float* eps_b  = (const float*)d_in[16];
    const float* eps_hw = (const float*)d_in[17];
    const float* eps_hb = (const float*)d_in[18];
    const int* task32   = (const int*)d_in[19];
    float* out = (float*)d_out;

    // Unconditional (no static guards — harness rule). Idempotent, non-stream call.
    cudaFuncSetAttribute(gemm_split_kernel,
                         cudaFuncAttributeMaxDynamicSharedMemorySize, DYN_SMEM);

    detect_task_kernel<<<1, 256>>>(task32);

    int n4;
    n4 = BATCH * IN_DIM / 4;
    split_x4_kernel<<<(n4 + 255) / 256, 256>>>((const float4*)x, n4);
    n4 = HID * IN_DIM / 4;
    gen_split_w4_kernel<<<(n4 + 255) / 256, 256>>>(
        (const float4*)mu_w0, (const float4*)ls_w0, (const float4*)eps_w0, 0, n4);
    n4 = NEX * HID * HID / 4;
    gen_split_w4_kernel<<<(n4 + 255) / 256, 256>>>(
        (const float4*)mu_w, (const float4*)ls_w, (const float4*)eps_w, 1, n4);

    int n;
    n = HID;
    gen_f32_kernel<<<(n + 255) / 256, 256>>>(mu_b0, ls_b0, eps_b0, 0, n);
    n = NEX * HID;
    gen_f32_kernel<<<(n + 255) / 256, 256>>>(mu_b, ls_b, eps_b, 1, n);
    n = NT * OUTD * HID;
    gen_f32_kernel<<<(n + 255) / 256, 256>>>(mu_hw, ls_hw, eps_hw, 2, n);
    n = NT * OUTD;
    gen_f32_kernel<<<(n + 255) / 256, 256>>>(mu_hb, ls_hb, eps_hb, 3, n);

    dim3 grid(HID / BN, BATCH / BM);   // (16, 16)
    gemm_split_kernel<<<grid, GTHREADS, DYN_SMEM>>>(0, 0, 0);
    gemm_split_kernel<<<grid, GTHREADS, DYN_SMEM>>>(1, 0, 1);
    gemm_split_kernel<<<grid, GTHREADS, DYN_SMEM>>>(2, 1, 0);
    gemm_split_kernel<<<grid, GTHREADS, DYN_SMEM>>>(3, 0, 1);
    head_kernel<<<BATCH, 128>>>(1, task32, out);
}

// round 7
// speedup vs baseline: 1.4441x; 1.2912x over previous
#include <cuda_runtime.h>
#include <cuda_bf16.h>
#include <cuda_fp16.h>
#include <cstdint>
#include <cstddef>

#define IN_DIM 1024
#define HID    2048
#define OUTD   10
#define NEX    3
#define NT     10
#define BATCH  4096

// GEMM tiling
#define BM      256
#define BN      128
#define BK      32
#define GTHREADS 512
#define SA_HI   0u
#define SA_LO   20480u    // 256*80
#define SB      40960u    // +256*80
#define STAGE   51200u    // 40960 + 128*80
#define NSTAGE  3
#define DYN_SMEM (NSTAGE * STAGE)   // 153600 B

// ---------------- static device scratch ----------------
__device__ __align__(256) __half g_x_hi[(size_t)BATCH * IN_DIM];
__device__ __align__(256) __half g_x_lo[(size_t)BATCH * IN_DIM];
__device__ __align__(256) __half g_w0_f[(size_t)HID * IN_DIM];
__device__ __align__(256) __half g_w_f[(size_t)NEX * HID * HID];
__device__ __align__(256) float  g_bias[HID + NEX * HID];
__device__ __align__(256) float  g_hw[(size_t)NT * OUTD * HID];
__device__ __align__(256) float  g_hb[NT * OUTD];
__device__ __align__(256) __half g_h_hi[2][(size_t)BATCH * HID];
__device__ __align__(256) __half g_h_lo[2][(size_t)BATCH * HID];
__device__ int g_task_is64;

// ---------------- task dtype detection (validated) ----------------
__global__ void detect_task_kernel(const int* __restrict__ t32) {
    __shared__ int any;
    if (threadIdx.x == 0) any = 0;
    __syncthreads();
    int local = 0;
    for (int i = 1 + 2 * threadIdx.x; i < BATCH; i += 2 * blockDim.x) local |= t32[i];
    if (local) atomicOr(&any, 1);
    __syncthreads();
    if (threadIdx.x == 0) g_task_is64 = (any == 0) ? 1 : 0;
}

// ---------------- elementwise generation ----------------
__device__ __forceinline__ void split1h(float v, unsigned short& h, unsigned short& l) {
    __half hb = __float2half_rn(v);
    __half lb = __float2half_rn(v - __half2float(hb));
    h = __half_as_ushort(hb);
    l = __half_as_ushort(lb);
}

__global__ void split_x4_kernel(const float4* __restrict__ x, int n4) {
    int i = blockIdx.x * blockDim.x + threadIdx.x;
    if (i >= n4) return;
    float4 v = x[i];
    unsigned short h0, h1, h2, h3, l0, l1, l2, l3;
    split1h(v.x, h0, l0); split1h(v.y, h1, l1); split1h(v.z, h2, l2); split1h(v.w, h3, l3);
    uint2 H, L;
    H.x = (uint32_t)h0 | ((uint32_t)h1 << 16); H.y = (uint32_t)h2 | ((uint32_t)h3 << 16);
    L.x = (uint32_t)l0 | ((uint32_t)l1 << 16); L.y = (uint32_t)l2 | ((uint32_t)l3 << 16);
    reinterpret_cast<uint2*>(g_x_hi)[i] = H;
    reinterpret_cast<uint2*>(g_x_lo)[i] = L;
}

// weights: single fp16
__global__ void gen_w4_kernel(const float4* __restrict__ mu,
                              const float4* __restrict__ ls,
                              const float4* __restrict__ eps,
                              int which, int n4) {
    int i = blockIdx.x * blockDim.x + threadIdx.x;
    if (i >= n4) return;
    float4 m = mu[i], l = ls[i], e = eps[i];
    unsigned short q0 = __half_as_ushort(__float2half_rn(fmaf(expf(l.x), e.x, m.x)));
    unsigned short q1 = __half_as_ushort(__float2half_rn(fmaf(expf(l.y), e.y, m.y)));
    unsigned short q2 = __half_as_ushort(__float2half_rn(fmaf(expf(l.z), e.z, m.z)));
    unsigned short q3 = __half_as_ushort(__float2half_rn(fmaf(expf(l.w), e.w, m.w)));
    uint2 P;
    P.x = (uint32_t)q0 | ((uint32_t)q1 << 16);
    P.y = (uint32_t)q2 | ((uint32_t)q3 << 16);
    if (which == 0) reinterpret_cast<uint2*>(g_w0_f)[i] = P;
    else            reinterpret_cast<uint2*>(g_w_f)[i]  = P;
}

__global__ void gen_f32_kernel(const float* __restrict__ mu,
                               const float* __restrict__ ls,
                               const float* __restrict__ eps,
                               int which, int n) {
    int i = blockIdx.x * blockDim.x + threadIdx.x;
    if (i >= n) return;
    float w = fmaf(expf(ls[i]), eps[i], mu[i]);
    float* dst = (which == 0) ? g_bias
               : (which == 1) ? (g_bias + HID)
               : (which == 2) ? g_hw
               :                g_hb;
    dst[i] = w;
}

// ---------------- HMMA primitives ----------------
__device__ __forceinline__ void ldsm4(uint32_t d[4], uint32_t addr) {
    asm volatile("ldmatrix.sync.aligned.m8n8.x4.shared.b16 {%0,%1,%2,%3}, [%4];"
                 : "=r"(d[0]), "=r"(d[1]), "=r"(d[2]), "=r"(d[3]) : "r"(addr));
}

__device__ __forceinline__ void mma_f16(float c[4], const uint32_t a[4], const uint32_t b[2]) {
    asm volatile("mma.sync.aligned.m16n8k16.row.col.f32.f16.f16.f32 "
                 "{%0,%1,%2,%3}, {%4,%5,%6,%7}, {%8,%9}, {%0,%1,%2,%3};"
                 : "+f"(c[0]), "+f"(c[1]), "+f"(c[2]), "+f"(c[3])
                 : "r"(a[0]), "r"(a[1]), "r"(a[2]), "r"(a[3]), "r"(b[0]), "r"(b[1]));
}

__device__ __forceinline__ void cp16(uint32_t dst, const void* src) {
    asm volatile("cp.async.cg.shared.global [%0], [%1], 16;" :: "r"(dst), "l"(src) : "memory");
}

// load one BK=32 chunk: A hi+lo (2x 256x32 fp16), B single (128x32 fp16); 5 cp16/thread
__device__ __forceinline__ void load_chunk(
    uint32_t sb,
    const __half* __restrict__ Ahi, const __half* __restrict__ Alo,
    const __half* __restrict__ W,
    int K, int m0, int n0, int kc, int tid)
{
#pragma unroll
    for (int j = 0; j < 2; j++) {        // A: 256 rows x 4 16B-chunks = 1024 lines
        int idx = tid + j * GTHREADS;
        int row = idx >> 2, ch = idx & 3;
        uint32_t dst = sb + (uint32_t)(row * 80 + ch * 16);
        size_t g = (size_t)(m0 + row) * K + kc + ch * 8;
        cp16(dst + SA_HI, Ahi + g);
        cp16(dst + SA_LO, Alo + g);
    }
    {                                    // B: 128 rows x 4 chunks = 512 lines
        int row = tid >> 2, ch = tid & 3;
        uint32_t dst = sb + (uint32_t)(row * 80 + ch * 16);
        size_t g = (size_t)(n0 + row) * K + kc + ch * 8;
        cp16(dst + SB, W + g);
    }
}

// ---------------- 2-term fp16 GEMM: C = relu(A*W^T + bias), re-split ----------------
__global__ __launch_bounds__(GTHREADS, 1) void gemm_split_kernel(int layer, int a_sel, int out_sel) {
    const __half *Ahi, *Alo, *W;
    const float* bias;
    int K;
    if (layer == 0) {
        Ahi = g_x_hi; Alo = g_x_lo; W = g_w0_f;
        bias = g_bias; K = IN_DIM;
    } else {
        Ahi = g_h_hi[a_sel]; Alo = g_h_lo[a_sel];
        W = g_w_f + (size_t)(layer - 1) * HID * HID;
        bias = g_bias + layer * HID; K = HID;
    }
    __half* Chi = g_h_hi[out_sel];
    __half* Clo = g_h_lo[out_sel];
    const int NC = K / BK;

    extern __shared__ __align__(128) uint8_t dyn[];
    const uint32_t sbase = (uint32_t)__cvta_generic_to_shared(dyn);

    const int tid  = threadIdx.x;
    const int warp = tid >> 5;
    const int lane = tid & 31;
    const int m0 = blockIdx.y * BM;
    const int n0 = blockIdx.x * BN;
    const int wm0 = (warp & 3) * 64;    // 4 warps along M, tile 64
    const int wn0 = (warp >> 2) * 32;   // 4 warps along N, tile 32

    float acc[4][4][4];
#pragma unroll
    for (int mt = 0; mt < 4; mt++)
#pragma unroll
        for (int nt = 0; nt < 4; nt++)
#pragma unroll
            for (int i = 0; i < 4; i++) acc[mt][nt][i] = 0.f;

    // prologue: chunks 0,1 -> stages 0,1
    load_chunk(sbase,         Ahi, Alo, W, K, m0, n0, 0,  tid);
    asm volatile("cp.async.commit_group;" ::: "memory");
    load_chunk(sbase + STAGE, Ahi, Alo, W, K, m0, n0, BK, tid);
    asm volatile("cp.async.commit_group;" ::: "memory");

    for (int i = 0; i < NC; i++) {
        if (i + 1 < NC) asm volatile("cp.async.wait_group 1;" ::: "memory");
        else            asm volatile("cp.async.wait_group 0;" ::: "memory");
        __syncthreads();
        if (i + 2 < NC) {
            load_chunk(sbase + (uint32_t)((i + 2) % NSTAGE) * STAGE,
                       Ahi, Alo, W, K, m0, n0, (i + 2) * BK, tid);
            asm volatile("cp.async.commit_group;" ::: "memory");
        }

        const uint32_t sb = sbase + (uint32_t)(i % NSTAGE) * STAGE;
#pragma unroll
        for (int kk = 0; kk < BK; kk += 16) {
            // A fragments: 4 m16 tiles, hi+lo
            uint32_t ahi[4][4], alo[4][4];
            const int rA  = lane & 15;
            const int chA = (kk >> 3) + (lane >> 4);
#pragma unroll
            for (int mt = 0; mt < 4; mt++) {
                uint32_t off = (uint32_t)((wm0 + mt * 16 + rA) * 80 + chA * 16);
                ldsm4(ahi[mt], sb + SA_HI + off);
                ldsm4(alo[mt], sb + SA_LO + off);
            }
            // B: single term; two x4 loads cover 4 n8 tiles
            const int rB  = (lane & 7) + ((lane >> 4) << 3);
            const int chB = (kk >> 3) + ((lane >> 3) & 1);
#pragma unroll
            for (int np = 0; np < 2; np++) {
                uint32_t off = (uint32_t)((wn0 + np * 16 + rB) * 80 + chB * 16);
                uint32_t bf[4];
                ldsm4(bf, sb + SB + off);
#pragma unroll
                for (int sub = 0; sub < 2; sub++) {
                    const int nt = np * 2 + sub;
                    const uint32_t b2[2] = { bf[sub * 2], bf[sub * 2 + 1] };
#pragma unroll
                    for (int mt = 0; mt < 4; mt++) {
                        mma_f16(acc[mt][nt], ahi[mt], b2);
                        mma_f16(acc[mt][nt], alo[mt], b2);
                    }
                }
            }
        }
    }

    // ---- epilogue: bias + relu + split to fp16 hi/lo ----
    const int gid  = lane >> 2;
    const int tid4 = lane & 3;
#pragma unroll
    for (int nt = 0; nt < 4; nt++) {
        const int col = n0 + wn0 + nt * 8 + tid4 * 2;
        const float bz0 = bias[col];
        const float bz1 = bias[col + 1];
#pragma unroll
        for (int mt = 0; mt < 4; mt++) {
            const int rowm = m0 + wm0 + mt * 16 + gid;
            const float* a = acc[mt][nt];
            {
                float v0 = fmaxf(a[0] + bz0, 0.f);
                float v1 = fmaxf(a[1] + bz1, 0.f);
                __half h0 = __float2half_rn(v0);
                __half h1 = __float2half_rn(v1);
                __half l0 = __float2half_rn(v0 - __half2float(h0));
                __half l1 = __float2half_rn(v1 - __half2float(h1));
                *reinterpret_cast<__half2*>(Chi + (size_t)rowm * HID + col) =
                    __halves2half2(h0, h1);
                *reinterpret_cast<__half2*>(Clo + (size_t)rowm * HID + col) =
                    __halves2half2(l0, l1);
            }
            {
                float v0 = fmaxf(a[2] + bz0, 0.f);
                float v1 = fmaxf(a[3] + bz1, 0.f);
                __half h0 = __float2half_rn(v0);
                __half h1 = __float2half_rn(v1);
                __half l0 = __float2half_rn(v0 - __half2float(h0));
                __half l1 = __float2half_rn(v1 - __half2float(h1));
                *reinterpret_cast<__half2*>(Chi + (size_t)(rowm + 8) * HID + col) =
                    __halves2half2(h0, h1);
                *reinterpret_cast<__half2*>(Clo + (size_t)(rowm + 8) * HID + col) =
                    __halves2half2(l0, l1);
            }
        }
    }
}

// ---------------- task-gathered multihead ----------------
__global__ __launch_bounds__(128) void head_kernel(int h_sel,
                                                   const int* __restrict__ task32,
                                                   float* __restrict__ out) {
    const int b = blockIdx.x;
    int t = g_task_is64 ? task32[2 * b] : task32[b];
    t = min(max(t, 0), NT - 1);

    const __half* hhi = g_h_hi[h_sel] + (size_t)b * HID;
    const __half* hlo = g_h_lo[h_sel] + (size_t)b * HID;
    const float* hw = g_hw + (size_t)t * OUTD * HID;

    float acc[OUTD];
#pragma unroll
    for (int o = 0; o < OUTD; o++) acc[o] = 0.f;

    for (int k = threadIdx.x; k < HID; k += blockDim.x) {
        float hv = __half2float(hhi[k]) + __half2float(hlo[k]);
#pragma unroll
        for (int o = 0; o < OUTD; o++) acc[o] = fmaf(hv, hw[(size_t)o * HID + k], acc[o]);
    }

    const int warp = threadIdx.x >> 5;
    const int lane = threadIdx.x & 31;
    __shared__ float red[4][OUTD];
#pragma unroll
    for (int o = 0; o < OUTD; o++) {
        float v = acc[o];
#pragma unroll
        for (int s = 16; s > 0; s >>= 1) v += __shfl_xor_sync(0xffffffffu, v, s);
        if (lane == 0) red[warp][o] = v;
    }
    __syncthreads();
    if (threadIdx.x < OUTD) {
        float s = red[0][threadIdx.x] + red[1][threadIdx.x] +
                  red[2][threadIdx.x] + red[3][threadIdx.x] +
                  g_hb[t * OUTD + threadIdx.x];
        out[(size_t)b * OUTD + threadIdx.x] = s;
    }
}

// ---------------- launch ----------------
extern "C" void kernel_launch(void* const* d_in, const int* in_sizes, int n_in,
                              void* d_out, int out_size) {
    (void)in_sizes; (void)n_in; (void)out_size;
    const float* x      = (const float*)d_in[0];
    const float* mu_w0  = (const float*)d_in[1];
    const float* ls_w0  = (const float*)d_in[2];
    const float* mu_b0  = (const float*)d_in[3];
    const float* ls_b0  = (const float*)d_in[4];
    const float* mu_w   = (const float*)d_in[5];
    const float* ls_w   = (const float*)d_in[6];
    const float* mu_b   = (const float*)d_in[7];
    const float* ls_b   = (const float*)d_in[8];
    const float* mu_hw  = (const float*)d_in[9];
    const float* ls_hw  = (const float*)d_in[10];
    const float* mu_hb  = (const float*)d_in[11];
    const float* ls_hb  = (const float*)d_in[12];
    const float* eps_w0 = (const float*)d_in[13];
    const float* eps_b0 = (const float*)d_in[14];
    const float* eps_w  = (const float*)d_in[15];
    const float* eps_b  = (const float*)d_in[16];
    const float* eps_hw = (const float*)d_in[17];
    const float* eps_hb = (const float*)d_in[18];
    const int* task32   = (const int*)d_in[19];
    float* out = (float*)d_out;

    cudaFuncSetAttribute(gemm_split_kernel,
                         cudaFuncAttributeMaxDynamicSharedMemorySize, DYN_SMEM);

    detect_task_kernel<<<1, 256>>>(task32);

    int n4;
    n4 = BATCH * IN_DIM / 4;
    split_x4_kernel<<<(n4 + 255) / 256, 256>>>((const float4*)x, n4);
    n4 = HID * IN_DIM / 4;
    gen_w4_kernel<<<(n4 + 255) / 256, 256>>>(
        (const float4*)mu_w0, (const float4*)ls_w0, (const float4*)eps_w0, 0, n4);
    n4 = NEX * HID * HID / 4;
    gen_w4_kernel<<<(n4 + 255) / 256, 256>>>(
        (const float4*)mu_w, (const float4*)ls_w, (const float4*)eps_w, 1, n4);

    int n;
    n = HID;
    gen_f32_kernel<<<(n + 255) / 256, 256>>>(mu_b0, ls_b0, eps_b0, 0, n);
    n = NEX * HID;
    gen_f32_kernel<<<(n + 255) / 256, 256>>>(mu_b, ls_b, eps_b, 1, n);
    n = NT * OUTD * HID;
    gen_f32_kernel<<<(n + 255) / 256, 256>>>(mu_hw, ls_hw, eps_hw, 2, n);
    n = NT * OUTD;
    gen_f32_kernel<<<(n + 255) / 256, 256>>>(mu_hb, ls_hb, eps_hb, 3, n);

    dim3 grid(HID / BN, BATCH / BM);   // (16, 16)
    gemm_split_kernel<<<grid, GTHREADS, DYN_SMEM>>>(0, 0, 0);
    gemm_split_kernel<<<grid, GTHREADS, DYN_SMEM>>>(1, 0, 1);
    gemm_split_kernel<<<grid, GTHREADS, DYN_SMEM>>>(2, 1, 0);
    gemm_split_kernel<<<grid, GTHREADS, DYN_SMEM>>>(3, 0, 1);
    head_kernel<<<BATCH, 128>>>(1, task32, out);
}

// round 8
// speedup vs baseline: 2.4381x; 1.6883x over previous
#include <cuda_runtime.h>
#include <cuda_fp16.h>
#include <cstdint>
#include <cstddef>

#define IN_DIM 1024
#define HID    2048
#define OUTD   10
#define NEX    3
#define NT     10
#define BATCH  4096

// GEMM tiling
#define BM      256
#define BN      128
#define BK      32
#define GTHREADS 512
#define SA      0u
#define SB      20480u    // 256*80
#define STAGE   30720u    // + 128*80
#define NSTAGE  3
#define DYN_SMEM (NSTAGE * STAGE)   // 92160 B

// ---------------- static device scratch ----------------
__device__ __align__(256) __half g_x_f[(size_t)BATCH * IN_DIM];
__device__ __align__(256) __half g_w0_f[(size_t)HID * IN_DIM];
__device__ __align__(256) __half g_w_f[(size_t)NEX * HID * HID];
__device__ __align__(256) float  g_bias[HID + NEX * HID];
__device__ __align__(256) float  g_hw[(size_t)NT * OUTD * HID];
__device__ __align__(256) float  g_hb[NT * OUTD];
__device__ __align__(256) __half g_h[2][(size_t)BATCH * HID];
__device__ int g_task_is64;

// ---------------- task dtype detection (validated) ----------------
__global__ void detect_task_kernel(const int* __restrict__ t32) {
    __shared__ int any;
    if (threadIdx.x == 0) any = 0;
    __syncthreads();
    int local = 0;
    for (int i = 1 + 2 * threadIdx.x; i < BATCH; i += 2 * blockDim.x) local |= t32[i];
    if (local) atomicOr(&any, 1);
    __syncthreads();
    if (threadIdx.x == 0) g_task_is64 = (any == 0) ? 1 : 0;
}

// ---------------- elementwise generation ----------------
__global__ void quant_x4_kernel(const float4* __restrict__ x, int n4) {
    int i = blockIdx.x * blockDim.x + threadIdx.x;
    if (i >= n4) return;
    float4 v = x[i];
    unsigned short q0 = __half_as_ushort(__float2half_rn(v.x));
    unsigned short q1 = __half_as_ushort(__float2half_rn(v.y));
    unsigned short q2 = __half_as_ushort(__float2half_rn(v.z));
    unsigned short q3 = __half_as_ushort(__float2half_rn(v.w));
    uint2 P;
    P.x = (uint32_t)q0 | ((uint32_t)q1 << 16);
    P.y = (uint32_t)q2 | ((uint32_t)q3 << 16);
    reinterpret_cast<uint2*>(g_x_f)[i] = P;
}

__global__ void gen_w4_kernel(const float4* __restrict__ mu,
                              const float4* __restrict__ ls,
                              const float4* __restrict__ eps,
                              int which, int n4) {
    int i = blockIdx.x * blockDim.x + threadIdx.x;
    if (i >= n4) return;
    float4 m = mu[i], l = ls[i], e = eps[i];
    unsigned short q0 = __half_as_ushort(__float2half_rn(fmaf(expf(l.x), e.x, m.x)));
    unsigned short q1 = __half_as_ushort(__float2half_rn(fmaf(expf(l.y), e.y, m.y)));
    unsigned short q2 = __half_as_ushort(__float2half_rn(fmaf(expf(l.z), e.z, m.z)));
    unsigned short q3 = __half_as_ushort(__float2half_rn(fmaf(expf(l.w), e.w, m.w)));
    uint2 P;
    P.x = (uint32_t)q0 | ((uint32_t)q1 << 16);
    P.y = (uint32_t)q2 | ((uint32_t)q3 << 16);
    if (which == 0) reinterpret_cast<uint2*>(g_w0_f)[i] = P;
    else            reinterpret_cast<uint2*>(g_w_f)[i]  = P;
}

__global__ void gen_f32_kernel(const float* __restrict__ mu,
                               const float* __restrict__ ls,
                               const float* __restrict__ eps,
                               int which, int n) {
    int i = blockIdx.x * blockDim.x + threadIdx.x;
    if (i >= n) return;
    float w = fmaf(expf(ls[i]), eps[i], mu[i]);
    float* dst = (which == 0) ? g_bias
               : (which == 1) ? (g_bias + HID)
               : (which == 2) ? g_hw
               :                g_hb;
    dst[i] = w;
}

// ---------------- HMMA primitives ----------------
__device__ __forceinline__ void ldsm4(uint32_t d[4], uint32_t addr) {
    asm volatile("ldmatrix.sync.aligned.m8n8.x4.shared.b16 {%0,%1,%2,%3}, [%4];"
                 : "=r"(d[0]), "=r"(d[1]), "=r"(d[2]), "=r"(d[3]) : "r"(addr));
}

__device__ __forceinline__ void mma_f16(float c[4], const uint32_t a[4], const uint32_t b[2]) {
    asm volatile("mma.sync.aligned.m16n8k16.row.col.f32.f16.f16.f32 "
                 "{%0,%1,%2,%3}, {%4,%5,%6,%7}, {%8,%9}, {%0,%1,%2,%3};"
                 : "+f"(c[0]), "+f"(c[1]), "+f"(c[2]), "+f"(c[3])
                 : "r"(a[0]), "r"(a[1]), "r"(a[2]), "r"(a[3]), "r"(b[0]), "r"(b[1]));
}

__device__ __forceinline__ void cp16(uint32_t dst, const void* src) {
    asm volatile("cp.async.cg.shared.global [%0], [%1], 16;" :: "r"(dst), "l"(src) : "memory");
}

// load one BK=32 chunk: A (256x32 fp16) + B (128x32 fp16); 3 cp16/thread
__device__ __forceinline__ void load_chunk(
    uint32_t sb,
    const __half* __restrict__ A, const __half* __restrict__ W,
    int K, int m0, int n0, int kc, int tid)
{
#pragma unroll
    for (int j = 0; j < 2; j++) {        // A: 256 rows x 4 16B-chunks = 1024 lines
        int idx = tid + j * GTHREADS;
        int row = idx >> 2, ch = idx & 3;
        uint32_t dst = sb + SA + (uint32_t)(row * 80 + ch * 16);
        size_t g = (size_t)(m0 + row) * K + kc + ch * 8;
        cp16(dst, A + g);
    }
    {                                    // B: 128 rows x 4 chunks = 512 lines
        int row = tid >> 2, ch = tid & 3;
        uint32_t dst = sb + SB + (uint32_t)(row * 80 + ch * 16);
        size_t g = (size_t)(n0 + row) * K + kc + ch * 8;
        cp16(dst, W + g);
    }
}

// ---------------- fp16 GEMM: C = relu(A*W^T + bias) ----------------
__global__ __launch_bounds__(GTHREADS, 1) void gemm_kernel(int layer, int a_sel, int out_sel) {
    const __half *A, *W;
    const float* bias;
    int K;
    if (layer == 0) {
        A = g_x_f; W = g_w0_f;
        bias = g_bias; K = IN_DIM;
    } else {
        A = g_h[a_sel];
        W = g_w_f + (size_t)(layer - 1) * HID * HID;
        bias = g_bias + layer * HID; K = HID;
    }
    __half* C = g_h[out_sel];
    const int NC = K / BK;

    extern __shared__ __align__(128) uint8_t dyn[];
    const uint32_t sbase = (uint32_t)__cvta_generic_to_shared(dyn);

    const int tid  = threadIdx.x;
    const int warp = tid >> 5;
    const int lane = tid & 31;
    const int m0 = blockIdx.y * BM;
    const int n0 = blockIdx.x * BN;
    const int wm0 = (warp & 3) * 64;    // 4 warps along M, tile 64
    const int wn0 = (warp >> 2) * 32;   // 4 warps along N, tile 32

    float acc[4][4][4];
#pragma unroll
    for (int mt = 0; mt < 4; mt++)
#pragma unroll
        for (int nt = 0; nt < 4; nt++)
#pragma unroll
            for (int i = 0; i < 4; i++) acc[mt][nt][i] = 0.f;

    // prologue: chunks 0,1 -> stages 0,1
    load_chunk(sbase,         A, W, K, m0, n0, 0,  tid);
    asm volatile("cp.async.commit_group;" ::: "memory");
    load_chunk(sbase + STAGE, A, W, K, m0, n0, BK, tid);
    asm volatile("cp.async.commit_group;" ::: "memory");

    for (int i = 0; i < NC; i++) {
        if (i + 1 < NC) asm volatile("cp.async.wait_group 1;" ::: "memory");
        else            asm volatile("cp.async.wait_group 0;" ::: "memory");
        __syncthreads();
        if (i + 2 < NC) {
            load_chunk(sbase + (uint32_t)((i + 2) % NSTAGE) * STAGE,
                       A, W, K, m0, n0, (i + 2) * BK, tid);
            asm volatile("cp.async.commit_group;" ::: "memory");
        }

        const uint32_t sb = sbase + (uint32_t)(i % NSTAGE) * STAGE;
#pragma unroll
        for (int kk = 0; kk < BK; kk += 16) {
            // A fragments: 4 m16 tiles
            uint32_t af[4][4];
            const int rA  = lane & 15;
            const int chA = (kk >> 3) + (lane >> 4);
#pragma unroll
            for (int mt = 0; mt < 4; mt++) {
                uint32_t off = (uint32_t)((wm0 + mt * 16 + rA) * 80 + chA * 16);
                ldsm4(af[mt], sb + SA + off);
            }
            // B: two x4 loads cover 4 n8 tiles
            const int rB  = (lane & 7) + ((lane >> 4) << 3);
            const int chB = (kk >> 3) + ((lane >> 3) & 1);
#pragma unroll
            for (int np = 0; np < 2; np++) {
                uint32_t off = (uint32_t)((wn0 + np * 16 + rB) * 80 + chB * 16);
                uint32_t bf[4];
                ldsm4(bf, sb + SB + off);
#pragma unroll
                for (int sub = 0; sub < 2; sub++) {
                    const int nt = np * 2 + sub;
                    const uint32_t b2[2] = { bf[sub * 2], bf[sub * 2 + 1] };
#pragma unroll
                    for (int mt = 0; mt < 4; mt++) {
                        mma_f16(acc[mt][nt], af[mt], b2);
                    }
                }
            }
        }
    }

    // ---- epilogue: bias + relu -> fp16 ----
    const int gid  = lane >> 2;
    const int tid4 = lane & 3;
#pragma unroll
    for (int nt = 0; nt < 4; nt++) {
        const int col = n0 + wn0 + nt * 8 + tid4 * 2;
        const float bz0 = bias[col];
        const float bz1 = bias[col + 1];
#pragma unroll
        for (int mt = 0; mt < 4; mt++) {
            const int rowm = m0 + wm0 + mt * 16 + gid;
            const float* a = acc[mt][nt];
            {
                float v0 = fmaxf(a[0] + bz0, 0.f);
                float v1 = fmaxf(a[1] + bz1, 0.f);
                *reinterpret_cast<__half2*>(C + (size_t)rowm * HID + col) =
                    __halves2half2(__float2half_rn(v0), __float2half_rn(v1));
            }
            {
                float v0 = fmaxf(a[2] + bz0, 0.f);
                float v1 = fmaxf(a[3] + bz1, 0.f);
                *reinterpret_cast<__half2*>(C + (size_t)(rowm + 8) * HID + col) =
                    __halves2half2(__float2half_rn(v0), __float2half_rn(v1));
            }
        }
    }
}

// ---------------- task-gathered multihead ----------------
__global__ __launch_bounds__(128) void head_kernel(int h_sel,
                                                   const int* __restrict__ task32,
                                                   float* __restrict__ out) {
    const int b = blockIdx.x;
    int t = g_task_is64 ? task32[2 * b] : task32[b];
    t = min(max(t, 0), NT - 1);

    const __half* h = g_h[h_sel] + (size_t)b * HID;
    const float* hw = g_hw + (size_t)t * OUTD * HID;

    float acc[OUTD];
#pragma unroll
    for (int o = 0; o < OUTD; o++) acc[o] = 0.f;

    for (int k = threadIdx.x; k < HID; k += blockDim.x) {
        float hv = __half2float(h[k]);
#pragma unroll
        for (int o = 0; o < OUTD; o++) acc[o] = fmaf(hv, hw[(size_t)o * HID + k], acc[o]);
    }

    const int warp = threadIdx.x >> 5;
    const int lane = threadIdx.x & 31;
    __shared__ float red[4][OUTD];
#pragma unroll
    for (int o = 0; o < OUTD; o++) {
        float v = acc[o];
#pragma unroll
        for (int s = 16; s > 0; s >>= 1) v += __shfl_xor_sync(0xffffffffu, v, s);
        if (lane == 0) red[warp][o] = v;
    }
    __syncthreads();
    if (threadIdx.x < OUTD) {
        float s = red[0][threadIdx.x] + red[1][threadIdx.x] +
                  red[2][threadIdx.x] + red[3][threadIdx.x] +
                  g_hb[t * OUTD + threadIdx.x];
        out[(size_t)b * OUTD + threadIdx.x] = s;
    }
}

// ---------------- launch ----------------
extern "C" void kernel_launch(void* const* d_in, const int* in_sizes, int n_in,
                              void* d_out, int out_size) {
    (void)in_sizes; (void)n_in; (void)out_size;
    const float* x      = (const float*)d_in[0];
    const float* mu_w0  = (const float*)d_in[1];
    const float* ls_w0  = (const float*)d_in[2];
    const float* mu_b0  = (const float*)d_in[3];
    const float* ls_b0  = (const float*)d_in[4];
    const float* mu_w   = (const float*)d_in[5];
    const float* ls_w   = (const float*)d_in[6];
    const float* mu_b   = (const float*)d_in[7];
    const float* ls_b   = (const float*)d_in[8];
    const float* mu_hw  = (const float*)d_in[9];
    const float* ls_hw  = (const float*)d_in[10];
    const float* mu_hb  = (const float*)d_in[11];
    const float* ls_hb  = (const float*)d_in[12];
    const float* eps_w0 = (const float*)d_in[13];
    const float* eps_b0 = (const float*)d_in[14];
    const float* eps_w  = (const float*)d_in[15];
    const float* eps_b  = (const float*)d_in[16];
    const float* eps_hw = (const float*)d_in[17];
    const float* eps_hb = (const float*)d_in[18];
    const int* task32   = (const int*)d_in[19];
    float* out = (float*)d_out;

    cudaFuncSetAttribute(gemm_kernel,
                         cudaFuncAttributeMaxDynamicSharedMemorySize, DYN_SMEM);

    detect_task_kernel<<<1, 256>>>(task32);

    int n4;
    n4 = BATCH * IN_DIM / 4;
    quant_x4_kernel<<<(n4 + 255) / 256, 256>>>((const float4*)x, n4);
    n4 = HID * IN_DIM / 4;
    gen_w4_kernel<<<(n4 + 255) / 256, 256>>>(
        (const float4*)mu_w0, (const float4*)ls_w0, (const float4*)eps_w0, 0, n4);
    n4 = NEX * HID * HID / 4;
    gen_w4_kernel<<<(n4 + 255) / 256, 256>>>(
        (const float4*)mu_w, (const float4*)ls_w, (const float4*)eps_w, 1, n4);

    int n;
    n = HID;
    gen_f32_kernel<<<(n + 255) / 256, 256>>>(mu_b0, ls_b0, eps_b0, 0, n);
    n = NEX * HID;
    gen_f32_kernel<<<(n + 255) / 256, 256>>>(mu_b, ls_b, eps_b, 1, n);
    n = NT * OUTD * HID;
    gen_f32_kernel<<<(n + 255) / 256, 256>>>(mu_hw, ls_hw, eps_hw, 2, n);
    n = NT * OUTD;
    gen_f32_kernel<<<(n + 255) / 256, 256>>>(mu_hb, ls_hb, eps_hb, 3, n);

    dim3 grid(HID / BN, BATCH / BM);   // (16, 16)
    gemm_kernel<<<grid, GTHREADS, DYN_SMEM>>>(0, 0, 0);
    gemm_kernel<<<grid, GTHREADS, DYN_SMEM>>>(1, 0, 1);
    gemm_kernel<<<grid, GTHREADS, DYN_SMEM>>>(2, 1, 0);
    gemm_kernel<<<grid, GTHREADS, DYN_SMEM>>>(3, 0, 1);
    head_kernel<<<BATCH, 128>>>(1, task32, out);
}

// round 9
// speedup vs baseline: 2.6404x; 1.0830x over previous
#include <cuda_runtime.h>
#include <cuda_fp16.h>
#include <cstdint>
#include <cstddef>

#define IN_DIM 1024
#define HID    2048
#define OUTD   10
#define NEX    3
#define NT     10
#define BATCH  4096

// GEMM tiling: 2 CTAs/SM
#define BM      128
#define BN      128
#define BK      32
#define GTHREADS 256
#define SA      0u
#define SB      10240u    // 128*80
#define STAGE   20480u
#define NSTAGE  4
#define DYN_SMEM (NSTAGE * STAGE)   // 81920 B -> 2 CTAs/SM (163840 <= 227KB)

// ---------------- static device scratch ----------------
__device__ __align__(256) __half g_x_f[(size_t)BATCH * IN_DIM];
__device__ __align__(256) __half g_w0_f[(size_t)HID * IN_DIM];
__device__ __align__(256) __half g_w_f[(size_t)NEX * HID * HID];
__device__ __align__(256) float  g_bias[HID + NEX * HID];
__device__ __align__(256) float  g_hw[(size_t)NT * OUTD * HID];
__device__ __align__(256) float  g_hb[NT * OUTD];
__device__ __align__(256) __half g_h[2][(size_t)BATCH * HID];
__device__ int g_task_is64;

// ---------------- task dtype detection (validated) ----------------
__global__ void detect_task_kernel(const int* __restrict__ t32) {
    __shared__ int any;
    if (threadIdx.x == 0) any = 0;
    __syncthreads();
    int local = 0;
    for (int i = 1 + 2 * threadIdx.x; i < BATCH; i += 2 * blockDim.x) local |= t32[i];
    if (local) atomicOr(&any, 1);
    __syncthreads();
    if (threadIdx.x == 0) g_task_is64 = (any == 0) ? 1 : 0;
}

// ---------------- elementwise generation ----------------
__global__ void quant_x4_kernel(const float4* __restrict__ x, int n4) {
    int i = blockIdx.x * blockDim.x + threadIdx.x;
    if (i >= n4) return;
    float4 v = x[i];
    unsigned short q0 = __half_as_ushort(__float2half_rn(v.x));
    unsigned short q1 = __half_as_ushort(__float2half_rn(v.y));
    unsigned short q2 = __half_as_ushort(__float2half_rn(v.z));
    unsigned short q3 = __half_as_ushort(__float2half_rn(v.w));
    uint2 P;
    P.x = (uint32_t)q0 | ((uint32_t)q1 << 16);
    P.y = (uint32_t)q2 | ((uint32_t)q3 << 16);
    reinterpret_cast<uint2*>(g_x_f)[i] = P;
}

__global__ void gen_w4_kernel(const float4* __restrict__ mu,
                              const float4* __restrict__ ls,
                              const float4* __restrict__ eps,
                              int which, int n4) {
    int i = blockIdx.x * blockDim.x + threadIdx.x;
    if (i >= n4) return;
    float4 m = mu[i], l = ls[i], e = eps[i];
    unsigned short q0 = __half_as_ushort(__float2half_rn(fmaf(expf(l.x), e.x, m.x)));
    unsigned short q1 = __half_as_ushort(__float2half_rn(fmaf(expf(l.y), e.y, m.y)));
    unsigned short q2 = __half_as_ushort(__float2half_rn(fmaf(expf(l.z), e.z, m.z)));
    unsigned short q3 = __half_as_ushort(__float2half_rn(fmaf(expf(l.w), e.w, m.w)));
    uint2 P;
    P.x = (uint32_t)q0 | ((uint32_t)q1 << 16);
    P.y = (uint32_t)q2 | ((uint32_t)q3 << 16);
    if (which == 0) reinterpret_cast<uint2*>(g_w0_f)[i] = P;
    else            reinterpret_cast<uint2*>(g_w_f)[i]  = P;
}

__global__ void gen_f32_kernel(const float* __restrict__ mu,
                               const float* __restrict__ ls,
                               const float* __restrict__ eps,
                               int which, int n) {
    int i = blockIdx.x * blockDim.x + threadIdx.x;
    if (i >= n) return;
    float w = fmaf(expf(ls[i]), eps[i], mu[i]);
    float* dst = (which == 0) ? g_bias
               : (which == 1) ? (g_bias + HID)
               : (which == 2) ? g_hw
               :                g_hb;
    dst[i] = w;
}

// ---------------- HMMA primitives ----------------
__device__ __forceinline__ void ldsm4(uint32_t d[4], uint32_t addr) {
    asm volatile("ldmatrix.sync.aligned.m8n8.x4.shared.b16 {%0,%1,%2,%3}, [%4];"
                 : "=r"(d[0]), "=r"(d[1]), "=r"(d[2]), "=r"(d[3]) : "r"(addr));
}

__device__ __forceinline__ void mma_f16(float c[4], const uint32_t a[4], const uint32_t b[2]) {
    asm volatile("mma.sync.aligned.m16n8k16.row.col.f32.f16.f16.f32 "
                 "{%0,%1,%2,%3}, {%4,%5,%6,%7}, {%8,%9}, {%0,%1,%2,%3};"
                 : "+f"(c[0]), "+f"(c[1]), "+f"(c[2]), "+f"(c[3])
                 : "r"(a[0]), "r"(a[1]), "r"(a[2]), "r"(a[3]), "r"(b[0]), "r"(b[1]));
}

__device__ __forceinline__ void cp16(uint32_t dst, const void* src) {
    asm volatile("cp.async.cg.shared.global [%0], [%1], 16;" :: "r"(dst), "l"(src) : "memory");
}

// load one BK=32 chunk: A (128x32 fp16) + B (128x32 fp16); 4 cp16/thread
__device__ __forceinline__ void load_chunk(
    uint32_t sb,
    const __half* __restrict__ A, const __half* __restrict__ W,
    int K, int m0, int n0, int kc, int tid)
{
#pragma unroll
    for (int j = 0; j < 2; j++) {        // A: 128 rows x 4 16B-chunks = 512 lines
        int idx = tid + j * GTHREADS;
        int row = idx >> 2, ch = idx & 3;
        uint32_t dst = sb + SA + (uint32_t)(row * 80 + ch * 16);
        size_t g = (size_t)(m0 + row) * K + kc + ch * 8;
        cp16(dst, A + g);
    }
#pragma unroll
    for (int j = 0; j < 2; j++) {        // B: 128 rows x 4 chunks = 512 lines
        int idx = tid + j * GTHREADS;
        int row = idx >> 2, ch = idx & 3;
        uint32_t dst = sb + SB + (uint32_t)(row * 80 + ch * 16);
        size_t g = (size_t)(n0 + row) * K + kc + ch * 8;
        cp16(dst, W + g);
    }
}

// ---------------- fp16 GEMM: C = relu(A*W^T + bias) ----------------
__global__ __launch_bounds__(GTHREADS, 2) void gemm_kernel(int layer, int a_sel, int out_sel) {
    const __half *A, *W;
    const float* bias;
    int K;
    if (layer == 0) {
        A = g_x_f; W = g_w0_f;
        bias = g_bias; K = IN_DIM;
    } else {
        A = g_h[a_sel];
        W = g_w_f + (size_t)(layer - 1) * HID * HID;
        bias = g_bias + layer * HID; K = HID;
    }
    __half* C = g_h[out_sel];
    const int NC = K / BK;

    extern __shared__ __align__(128) uint8_t dyn[];
    const uint32_t sbase = (uint32_t)__cvta_generic_to_shared(dyn);

    const int tid  = threadIdx.x;
    const int warp = tid >> 5;
    const int lane = tid & 31;
    const int m0 = blockIdx.y * BM;
    const int n0 = blockIdx.x * BN;
    const int wm0 = (warp & 1) * 64;    // 2 warps along M, tile 64
    const int wn0 = (warp >> 1) * 32;   // 4 warps along N, tile 32

    float acc[4][4][4];
#pragma unroll
    for (int mt = 0; mt < 4; mt++)
#pragma unroll
        for (int nt = 0; nt < 4; nt++)
#pragma unroll
            for (int i = 0; i < 4; i++) acc[mt][nt][i] = 0.f;

    // prologue: chunks 0,1,2 -> stages 0,1,2
    load_chunk(sbase,             A, W, K, m0, n0, 0,      tid);
    asm volatile("cp.async.commit_group;" ::: "memory");
    load_chunk(sbase + STAGE,     A, W, K, m0, n0, BK,     tid);
    asm volatile("cp.async.commit_group;" ::: "memory");
    load_chunk(sbase + 2 * STAGE, A, W, K, m0, n0, 2 * BK, tid);
    asm volatile("cp.async.commit_group;" ::: "memory");

    for (int i = 0; i < NC; i++) {
        // ensure chunk i is complete (newer chunks may still be pending)
        if (i + 2 < NC)      asm volatile("cp.async.wait_group 2;" ::: "memory");
        else if (i + 1 < NC) asm volatile("cp.async.wait_group 1;" ::: "memory");
        else                 asm volatile("cp.async.wait_group 0;" ::: "memory");
        __syncthreads();
        if (i + 3 < NC) {
            load_chunk(sbase + (uint32_t)((i + 3) % NSTAGE) * STAGE,
                       A, W, K, m0, n0, (i + 3) * BK, tid);
            asm volatile("cp.async.commit_group;" ::: "memory");
        }

        const uint32_t sb = sbase + (uint32_t)(i % NSTAGE) * STAGE;
#pragma unroll
        for (int kk = 0; kk < BK; kk += 16) {
            // A fragments: 4 m16 tiles
            uint32_t af[4][4];
            const int rA  = lane & 15;
            const int chA = (kk >> 3) + (lane >> 4);
#pragma unroll
            for (int mt = 0; mt < 4; mt++) {
                uint32_t off = (uint32_t)((wm0 + mt * 16 + rA) * 80 + chA * 16);
                ldsm4(af[mt], sb + SA + off);
            }
            // B: two x4 loads cover 4 n8 tiles
            const int rB  = (lane & 7) + ((lane >> 4) << 3);
            const int chB = (kk >> 3) + ((lane >> 3) & 1);
#pragma unroll
            for (int np = 0; np < 2; np++) {
                uint32_t off = (uint32_t)((wn0 + np * 16 + rB) * 80 + chB * 16);
                uint32_t bf[4];
                ldsm4(bf, sb + SB + off);
#pragma unroll
                for (int sub = 0; sub < 2; sub++) {
                    const int nt = np * 2 + sub;
                    const uint32_t b2[2] = { bf[sub * 2], bf[sub * 2 + 1] };
#pragma unroll
                    for (int mt = 0; mt < 4; mt++) {
                        mma_f16(acc[mt][nt], af[mt], b2);
                    }
                }
            }
        }
    }

    // ---- epilogue: bias + relu -> fp16 ----
    const int gid  = lane >> 2;
    const int tid4 = lane & 3;
#pragma unroll
    for (int nt = 0; nt < 4; nt++) {
        const int col = n0 + wn0 + nt * 8 + tid4 * 2;
        const float bz0 = bias[col];
        const float bz1 = bias[col + 1];
#pragma unroll
        for (int mt = 0; mt < 4; mt++) {
            const int rowm = m0 + wm0 + mt * 16 + gid;
            const float* a = acc[mt][nt];
            {
                float v0 = fmaxf(a[0] + bz0, 0.f);
                float v1 = fmaxf(a[1] + bz1, 0.f);
                *reinterpret_cast<__half2*>(C + (size_t)rowm * HID + col) =
                    __halves2half2(__float2half_rn(v0), __float2half_rn(v1));
            }
            {
                float v0 = fmaxf(a[2] + bz0, 0.f);
                float v1 = fmaxf(a[3] + bz1, 0.f);
                *reinterpret_cast<__half2*>(C + (size_t)(rowm + 8) * HID + col) =
                    __halves2half2(__float2half_rn(v0), __float2half_rn(v1));
            }
        }
    }
}

// ---------------- task-gathered multihead ----------------
__global__ __launch_bounds__(128) void head_kernel(int h_sel,
                                                   const int* __restrict__ task32,
                                                   float* __restrict__ out) {
    const int b = blockIdx.x;
    int t = g_task_is64 ? task32[2 * b] : task32[b];
    t = min(max(t, 0), NT - 1);

    const __half* h = g_h[h_sel] + (size_t)b * HID;
    const float* hw = g_hw + (size_t)t * OUTD * HID;

    float acc[OUTD];
#pragma unroll
    for (int o = 0; o < OUTD; o++) acc[o] = 0.f;

    for (int k = threadIdx.x; k < HID; k += blockDim.x) {
        float hv = __half2float(h[k]);
#pragma unroll
        for (int o = 0; o < OUTD; o++) acc[o] = fmaf(hv, hw[(size_t)o * HID + k], acc[o]);
    }

    const int warp = threadIdx.x >> 5;
    const int lane = threadIdx.x & 31;
    __shared__ float red[4][OUTD];
#pragma unroll
    for (int o = 0; o < OUTD; o++) {
        float v = acc[o];
#pragma unroll
        for (int s = 16; s > 0; s >>= 1) v += __shfl_xor_sync(0xffffffffu, v, s);
        if (lane == 0) red[warp][o] = v;
    }
    __syncthreads();
    if (threadIdx.x < OUTD) {
        float s = red[0][threadIdx.x] + red[1][threadIdx.x] +
                  red[2][threadIdx.x] + red[3][threadIdx.x] +
                  g_hb[t * OUTD + threadIdx.x];
        out[(size_t)b * OUTD + threadIdx.x] = s;
    }
}

// ---------------- launch ----------------
extern "C" void kernel_launch(void* const* d_in, const int* in_sizes, int n_in,
                              void* d_out, int out_size) {
    (void)in_sizes; (void)n_in; (void)out_size;
    const float* x      = (const float*)d_in[0];
    const float* mu_w0  = (const float*)d_in[1];
    const float* ls_w0  = (const float*)d_in[2];
    const float* mu_b0  = (const float*)d_in[3];
    const float* ls_b0  = (const float*)d_in[4];
    const float* mu_w   = (const float*)d_in[5];
    const float* ls_w   = (const float*)d_in[6];
    const float* mu_b   = (const float*)d_in[7];
    const float* ls_b   = (const float*)d_in[8];
    const float* mu_hw  = (const float*)d_in[9];
    const float* ls_hw  = (const float*)d_in[10];
    const float* mu_hb  = (const float*)d_in[11];
    const float* ls_hb  = (const float*)d_in[12];
    const float* eps_w0 = (const float*)d_in[13];
    const float* eps_b0 = (const float*)d_in[14];
    const float* eps_w  = (const float*)d_in[15];
    const float* eps_b  = (const float*)d_in[16];
    const float* eps_hw = (const float*)d_in[17];
    const float* eps_hb = (const float*)d_in[18];
    const int* task32   = (const int*)d_in[19];
    float* out = (float*)d_out;

    cudaFuncSetAttribute(gemm_kernel,
                         cudaFuncAttributeMaxDynamicSharedMemorySize, DYN_SMEM);

    detect_task_kernel<<<1, 256>>>(task32);

    int n4;
    n4 = BATCH * IN_DIM / 4;
    quant_x4_kernel<<<(n4 + 255) / 256, 256>>>((const float4*)x, n4);
    n4 = HID * IN_DIM / 4;
    gen_w4_kernel<<<(n4 + 255) / 256, 256>>>(
        (const float4*)mu_w0, (const float4*)ls_w0, (const float4*)eps_w0, 0, n4);
    n4 = NEX * HID * HID / 4;
    gen_w4_kernel<<<(n4 + 255) / 256, 256>>>(
        (const float4*)mu_w, (const float4*)ls_w, (const float4*)eps_w, 1, n4);

    int n;
    n = HID;
    gen_f32_kernel<<<(n + 255) / 256, 256>>>(mu_b0, ls_b0, eps_b0, 0, n);
    n = NEX * HID;
    gen_f32_kernel<<<(n + 255) / 256, 256>>>(mu_b, ls_b, eps_b, 1, n);
    n = NT * OUTD * HID;
    gen_f32_kernel<<<(n + 255) / 256, 256>>>(mu_hw, ls_hw, eps_hw, 2, n);
    n = NT * OUTD;
    gen_f32_kernel<<<(n + 255) / 256, 256>>>(mu_hb, ls_hb, eps_hb, 3, n);

    dim3 grid(HID / BN, BATCH / BM);   // (16, 32) = 512 CTAs
    gemm_kernel<<<grid, GTHREADS, DYN_SMEM>>>(0, 0, 0);
    gemm_kernel<<<grid, GTHREADS, DYN_SMEM>>>(1, 0, 1);
    gemm_kernel<<<grid, GTHREADS, DYN_SMEM>>>(2, 1, 0);
    gemm_kernel<<<grid, GTHREADS, DYN_SMEM>>>(3, 0, 1);
    head_kernel<<<BATCH, 128>>>(1, task32, out);
}

// round 10
// speedup vs baseline: 2.8437x; 1.0770x over previous
#include <cuda_runtime.h>
#include <cuda_fp16.h>
#include <cstdint>
#include <cstddef>

#define IN_DIM 1024
#define HID    2048
#define OUTD   10
#define NEX    3
#define NT     10
#define BATCH  4096

// GEMM tiling: 4 CTAs/SM, fine-grained tiles for SM load balance
#define BM      128
#define BN      64
#define BK      32
#define GTHREADS 128
#define SA      0u
#define SB      10240u    // 128*80
#define STAGE   15360u    // + 64*80
#define NSTAGE  3
#define DYN_SMEM (NSTAGE * STAGE)   // 46080 B -> 4 CTAs/SM (184320 <= 227KB)

// ---------------- static device scratch ----------------
__device__ __align__(256) __half g_x_f[(size_t)BATCH * IN_DIM];
__device__ __align__(256) __half g_w0_f[(size_t)HID * IN_DIM];
__device__ __align__(256) __half g_w_f[(size_t)NEX * HID * HID];
__device__ __align__(256) float  g_bias[HID + NEX * HID];
__device__ __align__(256) float  g_hw[(size_t)NT * OUTD * HID];
__device__ __align__(256) float  g_hb[NT * OUTD];
__device__ __align__(256) __half g_h[2][(size_t)BATCH * HID];
__device__ int g_task_is64;

// ---------------- task dtype detection (validated) ----------------
__global__ void detect_task_kernel(const int* __restrict__ t32) {
    __shared__ int any;
    if (threadIdx.x == 0) any = 0;
    __syncthreads();
    int local = 0;
    for (int i = 1 + 2 * threadIdx.x; i < BATCH; i += 2 * blockDim.x) local |= t32[i];
    if (local) atomicOr(&any, 1);
    __syncthreads();
    if (threadIdx.x == 0) g_task_is64 = (any == 0) ? 1 : 0;
}

// ---------------- elementwise generation ----------------
__global__ void quant_x4_kernel(const float4* __restrict__ x, int n4) {
    int i = blockIdx.x * blockDim.x + threadIdx.x;
    if (i >= n4) return;
    float4 v = x[i];
    unsigned short q0 = __half_as_ushort(__float2half_rn(v.x));
    unsigned short q1 = __half_as_ushort(__float2half_rn(v.y));
    unsigned short q2 = __half_as_ushort(__float2half_rn(v.z));
    unsigned short q3 = __half_as_ushort(__float2half_rn(v.w));
    uint2 P;
    P.x = (uint32_t)q0 | ((uint32_t)q1 << 16);
    P.y = (uint32_t)q2 | ((uint32_t)q3 << 16);
    reinterpret_cast<uint2*>(g_x_f)[i] = P;
}

__global__ void gen_w4_kernel(const float4* __restrict__ mu,
                              const float4* __restrict__ ls,
                              const float4* __restrict__ eps,
                              int which, int n4) {
    int i = blockIdx.x * blockDim.x + threadIdx.x;
    if (i >= n4) return;
    float4 m = mu[i], l = ls[i], e = eps[i];
    unsigned short q0 = __half_as_ushort(__float2half_rn(fmaf(expf(l.x), e.x, m.x)));
    unsigned short q1 = __half_as_ushort(__float2half_rn(fmaf(expf(l.y), e.y, m.y)));
    unsigned short q2 = __half_as_ushort(__float2half_rn(fmaf(expf(l.z), e.z, m.z)));
    unsigned short q3 = __half_as_ushort(__float2half_rn(fmaf(expf(l.w), e.w, m.w)));
    uint2 P;
    P.x = (uint32_t)q0 | ((uint32_t)q1 << 16);
    P.y = (uint32_t)q2 | ((uint32_t)q3 << 16);
    if (which == 0) reinterpret_cast<uint2*>(g_w0_f)[i] = P;
    else            reinterpret_cast<uint2*>(g_w_f)[i]  = P;
}

__global__ void gen_f32_kernel(const float* __restrict__ mu,
                               const float* __restrict__ ls,
                               const float* __restrict__ eps,
                               int which, int n) {
    int i = blockIdx.x * blockDim.x + threadIdx.x;
    if (i >= n) return;
    float w = fmaf(expf(ls[i]), eps[i], mu[i]);
    float* dst = (which == 0) ? g_bias
               : (which == 1) ? (g_bias + HID)
               : (which == 2) ? g_hw
               :                g_hb;
    dst[i] = w;
}

// ---------------- HMMA primitives ----------------
__device__ __forceinline__ void ldsm4(uint32_t d[4], uint32_t addr) {
    asm volatile("ldmatrix.sync.aligned.m8n8.x4.shared.b16 {%0,%1,%2,%3}, [%4];"
                 : "=r"(d[0]), "=r"(d[1]), "=r"(d[2]), "=r"(d[3]) : "r"(addr));
}

__device__ __forceinline__ void mma_f16(float c[4], const uint32_t a[4], const uint32_t b[2]) {
    asm volatile("mma.sync.aligned.m16n8k16.row.col.f32.f16.f16.f32 "
                 "{%0,%1,%2,%3}, {%4,%5,%6,%7}, {%8,%9}, {%0,%1,%2,%3};"
                 : "+f"(c[0]), "+f"(c[1]), "+f"(c[2]), "+f"(c[3])
                 : "r"(a[0]), "r"(a[1]), "r"(a[2]), "r"(a[3]), "r"(b[0]), "r"(b[1]));
}

__device__ __forceinline__ void cp16(uint32_t dst, const void* src) {
    asm volatile("cp.async.cg.shared.global [%0], [%1], 16;" :: "r"(dst), "l"(src) : "memory");
}

// load one BK=32 chunk: A (128x32 fp16) + B (64x32 fp16); 6 cp16/thread
__device__ __forceinline__ void load_chunk(
    uint32_t sb,
    const __half* __restrict__ A, const __half* __restrict__ W,
    int K, int m0, int n0, int kc, int tid)
{
#pragma unroll
    for (int j = 0; j < 4; j++) {        // A: 128 rows x 4 16B-chunks = 512 lines
        int idx = tid + j * GTHREADS;
        int row = idx >> 2, ch = idx & 3;
        uint32_t dst = sb + SA + (uint32_t)(row * 80 + ch * 16);
        size_t g = (size_t)(m0 + row) * K + kc + ch * 8;
        cp16(dst, A + g);
    }
#pragma unroll
    for (int j = 0; j < 2; j++) {        // B: 64 rows x 4 chunks = 256 lines
        int idx = tid + j * GTHREADS;
        int row = idx >> 2, ch = idx & 3;
        uint32_t dst = sb + SB + (uint32_t)(row * 80 + ch * 16);
        size_t g = (size_t)(n0 + row) * K + kc + ch * 8;
        cp16(dst, W + g);
    }
}

// ---------------- fp16 GEMM: C = relu(A*W^T + bias) ----------------
__global__ __launch_bounds__(GTHREADS, 4) void gemm_kernel(int layer, int a_sel, int out_sel) {
    const __half *A, *W;
    const float* bias;
    int K;
    if (layer == 0) {
        A = g_x_f; W = g_w0_f;
        bias = g_bias; K = IN_DIM;
    } else {
        A = g_h[a_sel];
        W = g_w_f + (size_t)(layer - 1) * HID * HID;
        bias = g_bias + layer * HID; K = HID;
    }
    __half* C = g_h[out_sel];
    const int NC = K / BK;

    extern __shared__ __align__(128) uint8_t dyn[];
    const uint32_t sbase = (uint32_t)__cvta_generic_to_shared(dyn);

    const int tid  = threadIdx.x;
    const int warp = tid >> 5;
    const int lane = tid & 31;
    const int m0 = blockIdx.y * BM;
    const int n0 = blockIdx.x * BN;
    const int wm0 = (warp & 1) * 64;    // 2 warps along M, tile 64
    const int wn0 = (warp >> 1) * 32;   // 2 warps along N, tile 32

    float acc[4][4][4];
#pragma unroll
    for (int mt = 0; mt < 4; mt++)
#pragma unroll
        for (int nt = 0; nt < 4; nt++)
#pragma unroll
            for (int i = 0; i < 4; i++) acc[mt][nt][i] = 0.f;

    // prologue: chunks 0,1 -> stages 0,1
    load_chunk(sbase,         A, W, K, m0, n0, 0,  tid);
    asm volatile("cp.async.commit_group;" ::: "memory");
    load_chunk(sbase + STAGE, A, W, K, m0, n0, BK, tid);
    asm volatile("cp.async.commit_group;" ::: "memory");

    for (int i = 0; i < NC; i++) {
        if (i + 1 < NC) asm volatile("cp.async.wait_group 1;" ::: "memory");
        else            asm volatile("cp.async.wait_group 0;" ::: "memory");
        __syncthreads();
        if (i + 2 < NC) {
            load_chunk(sbase + (uint32_t)((i + 2) % NSTAGE) * STAGE,
                       A, W, K, m0, n0, (i + 2) * BK, tid);
            asm volatile("cp.async.commit_group;" ::: "memory");
        }

        const uint32_t sb = sbase + (uint32_t)(i % NSTAGE) * STAGE;
#pragma unroll
        for (int kk = 0; kk < BK; kk += 16) {
            // A fragments: 4 m16 tiles
            uint32_t af[4][4];
            const int rA  = lane & 15;
            const int chA = (kk >> 3) + (lane >> 4);
#pragma unroll
            for (int mt = 0; mt < 4; mt++) {
                uint32_t off = (uint32_t)((wm0 + mt * 16 + rA) * 80 + chA * 16);
                ldsm4(af[mt], sb + SA + off);
            }
            // B: two x4 loads cover 4 n8 tiles
            const int rB  = (lane & 7) + ((lane >> 4) << 3);
            const int chB = (kk >> 3) + ((lane >> 3) & 1);
#pragma unroll
            for (int np = 0; np < 2; np++) {
                uint32_t off = (uint32_t)((wn0 + np * 16 + rB) * 80 + chB * 16);
                uint32_t bf[4];
                ldsm4(bf, sb + SB + off);
#pragma unroll
                for (int sub = 0; sub < 2; sub++) {
                    const int nt = np * 2 + sub;
                    const uint32_t b2[2] = { bf[sub * 2], bf[sub * 2 + 1] };
#pragma unroll
                    for (int mt = 0; mt < 4; mt++) {
                        mma_f16(acc[mt][nt], af[mt], b2);
                    }
                }
            }
        }
    }

    // ---- epilogue: bias + relu -> fp16 ----
    const int gid  = lane >> 2;
    const int tid4 = lane & 3;
#pragma unroll
    for (int nt = 0; nt < 4; nt++) {
        const int col = n0 + wn0 + nt * 8 + tid4 * 2;
        const float bz0 = bias[col];
        const float bz1 = bias[col + 1];
#pragma unroll
        for (int mt = 0; mt < 4; mt++) {
            const int rowm = m0 + wm0 + mt * 16 + gid;
            const float* a = acc[mt][nt];
            {
                float v0 = fmaxf(a[0] + bz0, 0.f);
                float v1 = fmaxf(a[1] + bz1, 0.f);
                *reinterpret_cast<__half2*>(C + (size_t)rowm * HID + col) =
                    __halves2half2(__float2half_rn(v0), __float2half_rn(v1));
            }
            {
                float v0 = fmaxf(a[2] + bz0, 0.f);
                float v1 = fmaxf(a[3] + bz1, 0.f);
                *reinterpret_cast<__half2*>(C + (size_t)(rowm + 8) * HID + col) =
                    __halves2half2(__float2half_rn(v0), __float2half_rn(v1));
            }
        }
    }
}

// ---------------- task-gathered multihead ----------------
__global__ __launch_bounds__(128) void head_kernel(int h_sel,
                                                   const int* __restrict__ task32,
                                                   float* __restrict__ out) {
    const int b = blockIdx.x;
    int t = g_task_is64 ? task32[2 * b] : task32[b];
    t = min(max(t, 0), NT - 1);

    const __half* h = g_h[h_sel] + (size_t)b * HID;
    const float* hw = g_hw + (size_t)t * OUTD * HID;

    float acc[OUTD];
#pragma unroll
    for (int o = 0; o < OUTD; o++) acc[o] = 0.f;

    for (int k = threadIdx.x; k < HID; k += blockDim.x) {
        float hv = __half2float(h[k]);
#pragma unroll
        for (int o = 0; o < OUTD; o++) acc[o] = fmaf(hv, hw[(size_t)o * HID + k], acc[o]);
    }

    const int warp = threadIdx.x >> 5;
    const int lane = threadIdx.x & 31;
    __shared__ float red[4][OUTD];
#pragma unroll
    for (int o = 0; o < OUTD; o++) {
        float v = acc[o];
#pragma unroll
        for (int s = 16; s > 0; s >>= 1) v += __shfl_xor_sync(0xffffffffu, v, s);
        if (lane == 0) red[warp][o] = v;
    }
    __syncthreads();
    if (threadIdx.x < OUTD) {
        float s = red[0][threadIdx.x] + red[1][threadIdx.x] +
                  red[2][threadIdx.x] + red[3][threadIdx.x] +
                  g_hb[t * OUTD + threadIdx.x];
        out[(size_t)b * OUTD + threadIdx.x] = s;
    }
}

// ---------------- launch ----------------
extern "C" void kernel_launch(void* const* d_in, const int* in_sizes, int n_in,
                              void* d_out, int out_size) {
    (void)in_sizes; (void)n_in; (void)out_size;
    const float* x      = (const float*)d_in[0];
    const float* mu_w0  = (const float*)d_in[1];
    const float* ls_w0  = (const float*)d_in[2];
    const float* mu_b0  = (const float*)d_in[3];
    const float* ls_b0  = (const float*)d_in[4];
    const float* mu_w   = (const float*)d_in[5];
    const float* ls_w   = (const float*)d_in[6];
    const float* mu_b   = (const float*)d_in[7];
    const float* ls_b   = (const float*)d_in[8];
    const float* mu_hw  = (const float*)d_in[9];
    const float* ls_hw  = (const float*)d_in[10];
    const float* mu_hb  = (const float*)d_in[11];
    const float* ls_hb  = (const float*)d_in[12];
    const float* eps_w0 = (const float*)d_in[13];
    const float* eps_b0 = (const float*)d_in[14];
    const float* eps_w  = (const float*)d_in[15];
    const float* eps_b  = (const float*)d_in[16];
    const float* eps_hw = (const float*)d_in[17];
    const float* eps_hb = (const float*)d_in[18];
    const int* task32   = (const int*)d_in[19];
    float* out = (float*)d_out;

    cudaFuncSetAttribute(gemm_kernel,
                         cudaFuncAttributeMaxDynamicSharedMemorySize, DYN_SMEM);

    detect_task_kernel<<<1, 256>>>(task32);

    int n4;
    n4 = BATCH * IN_DIM / 4;
    quant_x4_kernel<<<(n4 + 255) / 256, 256>>>((const float4*)x, n4);
    n4 = HID * IN_DIM / 4;
    gen_w4_kernel<<<(n4 + 255) / 256, 256>>>(
        (const float4*)mu_w0, (const float4*)ls_w0, (const float4*)eps_w0, 0, n4);
    n4 = NEX * HID * HID / 4;
    gen_w4_kernel<<<(n4 + 255) / 256, 256>>>(
        (const float4*)mu_w, (const float4*)ls_w, (const float4*)eps_w, 1, n4);

    int n;
    n = HID;
    gen_f32_kernel<<<(n + 255) / 256, 256>>>(mu_b0, ls_b0, eps_b0, 0, n);
    n = NEX * HID;
    gen_f32_kernel<<<(n + 255) / 256, 256>>>(mu_b, ls_b, eps_b, 1, n);
    n = NT * OUTD * HID;
    gen_f32_kernel<<<(n + 255) / 256, 256>>>(mu_hw, ls_hw, eps_hw, 2, n);
    n = NT * OUTD;
    gen_f32_kernel<<<(n + 255) / 256, 256>>>(mu_hb, ls_hb, eps_hb, 3, n);

    dim3 grid(HID / BN, BATCH / BM);   // (32, 32) = 1024 CTAs
    gemm_kernel<<<grid, GTHREADS, DYN_SMEM>>>(0, 0, 0);
    gemm_kernel<<<grid, GTHREADS, DYN_SMEM>>>(1, 0, 1);
    gemm_kernel<<<grid, GTHREADS, DYN_SMEM>>>(2, 1, 0);
    gemm_kernel<<<grid, GTHREADS, DYN_SMEM>>>(3, 0, 1);
    head_kernel<<<BATCH, 128>>>(1, task32, out);
}

// round 11
// speedup vs baseline: 2.8894x; 1.0161x over previous
#include <cuda_runtime.h>
#include <cuda_fp16.h>
#include <cstdint>
#include <cstddef>

#define IN_DIM 1024
#define HID    2048
#define OUTD   10
#define NEX    3
#define NT     10
#define BATCH  4096

// GEMM tiling: 4 CTAs/SM, fine-grained tiles for SM load balance
#define BM      128
#define BN      64
#define BK      32
#define GTHREADS 128
#define SA      0u
#define SB      10240u    // 128*80
#define STAGE   15360u    // + 64*80
#define NSTAGE  3
#define DYN_SMEM (NSTAGE * STAGE)   // 46080 B -> 4 CTAs/SM

// ---------------- static device scratch ----------------
__device__ __align__(256) __half g_x_f[(size_t)BATCH * IN_DIM];
__device__ __align__(256) __half g_w0_f[(size_t)HID * IN_DIM];
__device__ __align__(256) __half g_w_f[(size_t)NEX * HID * HID];
__device__ __align__(256) float  g_bias[HID + NEX * HID];
__device__ __align__(256) float  g_hw[(size_t)NT * OUTD * HID];
__device__ __align__(256) float  g_hb[NT * OUTD];
__device__ __align__(256) __half g_h[2][(size_t)BATCH * HID];
__device__ int g_task_is64;

// ---------------- fork/join stream + events (host-side objects, created once
// pre-capture; no device memory allocation) ----------------
static cudaStream_t g_side_stream;
static cudaEvent_t  g_ev_fork, g_ev_join;
static struct SideInit {
    SideInit() {
        cudaStreamCreateWithFlags(&g_side_stream, cudaStreamNonBlocking);
        cudaEventCreateWithFlags(&g_ev_fork, cudaEventDisableTiming);
        cudaEventCreateWithFlags(&g_ev_join, cudaEventDisableTiming);
    }
} g_side_init;

// ---------------- task dtype detection (validated) ----------------
__global__ void detect_task_kernel(const int* __restrict__ t32) {
    __shared__ int any;
    if (threadIdx.x == 0) any = 0;
    __syncthreads();
    int local = 0;
    for (int i = 1 + 2 * threadIdx.x; i < BATCH; i += 2 * blockDim.x) local |= t32[i];
    if (local) atomicOr(&any, 1);
    __syncthreads();
    if (threadIdx.x == 0) g_task_is64 = (any == 0) ? 1 : 0;
}

// ---------------- elementwise generation ----------------
__global__ void quant_x4_kernel(const float4* __restrict__ x, int n4) {
    int i = blockIdx.x * blockDim.x + threadIdx.x;
    if (i >= n4) return;
    float4 v = x[i];
    unsigned short q0 = __half_as_ushort(__float2half_rn(v.x));
    unsigned short q1 = __half_as_ushort(__float2half_rn(v.y));
    unsigned short q2 = __half_as_ushort(__float2half_rn(v.z));
    unsigned short q3 = __half_as_ushort(__float2half_rn(v.w));
    uint2 P;
    P.x = (uint32_t)q0 | ((uint32_t)q1 << 16);
    P.y = (uint32_t)q2 | ((uint32_t)q3 << 16);
    reinterpret_cast<uint2*>(g_x_f)[i] = P;
}

__global__ void gen_w4_kernel(const float4* __restrict__ mu,
                              const float4* __restrict__ ls,
                              const float4* __restrict__ eps,
                              int which, int n4) {
    int i = blockIdx.x * blockDim.x + threadIdx.x;
    if (i >= n4) return;
    float4 m = mu[i], l = ls[i], e = eps[i];
    unsigned short q0 = __half_as_ushort(__float2half_rn(fmaf(expf(l.x), e.x, m.x)));
    unsigned short q1 = __half_as_ushort(__float2half_rn(fmaf(expf(l.y), e.y, m.y)));
    unsigned short q2 = __half_as_ushort(__float2half_rn(fmaf(expf(l.z), e.z, m.z)));
    unsigned short q3 = __half_as_ushort(__float2half_rn(fmaf(expf(l.w), e.w, m.w)));
    uint2 P;
    P.x = (uint32_t)q0 | ((uint32_t)q1 << 16);
    P.y = (uint32_t)q2 | ((uint32_t)q3 << 16);
    if (which == 0) reinterpret_cast<uint2*>(g_w0_f)[i] = P;
    else            reinterpret_cast<uint2*>(g_w_f)[i]  = P;
}

// bias0 only (needed by gemm0 on the main stream)
__global__ void gen_bias0_kernel(const float* __restrict__ mu,
                                 const float* __restrict__ ls,
                                 const float* __restrict__ eps) {
    int i = blockIdx.x * blockDim.x + threadIdx.x;
    if (i < HID) g_bias[i] = fmaf(expf(ls[i]), eps[i], mu[i]);
}

// side-chain small gens merged: biases 1..3, head weights, head biases
__global__ void gen_rest_kernel(const float* __restrict__ mu_b,  const float* __restrict__ ls_b,  const float* __restrict__ eps_b,
                                const float* __restrict__ mu_hw, const float* __restrict__ ls_hw, const float* __restrict__ eps_hw,
                                const float* __restrict__ mu_hb, const float* __restrict__ ls_hb, const float* __restrict__ eps_hb) {
    const int n1 = NEX * HID;
    const int n2 = NT * OUTD * HID;
    const int n3 = NT * OUTD;
    int i = blockIdx.x * blockDim.x + threadIdx.x;
    if (i < n1) {
        g_bias[HID + i] = fmaf(expf(ls_b[i]), eps_b[i], mu_b[i]);
    } else if (i < n1 + n2) {
        int j = i - n1;
        g_hw[j] = fmaf(expf(ls_hw[j]), eps_hw[j], mu_hw[j]);
    } else if (i < n1 + n2 + n3) {
        int j = i - n1 - n2;
        g_hb[j] = fmaf(expf(ls_hb[j]), eps_hb[j], mu_hb[j]);
    }
}

// ---------------- HMMA primitives ----------------
__device__ __forceinline__ void ldsm4(uint32_t d[4], uint32_t addr) {
    asm volatile("ldmatrix.sync.aligned.m8n8.x4.shared.b16 {%0,%1,%2,%3}, [%4];"
                 : "=r"(d[0]), "=r"(d[1]), "=r"(d[2]), "=r"(d[3]) : "r"(addr));
}

__device__ __forceinline__ void mma_f16(float c[4], const uint32_t a[4], const uint32_t b[2]) {
    asm volatile("mma.sync.aligned.m16n8k16.row.col.f32.f16.f16.f32 "
                 "{%0,%1,%2,%3}, {%4,%5,%6,%7}, {%8,%9}, {%0,%1,%2,%3};"
                 : "+f"(c[0]), "+f"(c[1]), "+f"(c[2]), "+f"(c[3])
                 : "r"(a[0]), "r"(a[1]), "r"(a[2]), "r"(a[3]), "r"(b[0]), "r"(b[1]));
}

__device__ __forceinline__ void cp16(uint32_t dst, const void* src) {
    asm volatile("cp.async.cg.shared.global [%0], [%1], 16;" :: "r"(dst), "l"(src) : "memory");
}

// load one BK=32 chunk: A (128x32 fp16) + B (64x32 fp16); 6 cp16/thread
__device__ __forceinline__ void load_chunk(
    uint32_t sb,
    const __half* __restrict__ A, const __half* __restrict__ W,
    int K, int m0, int n0, int kc, int tid)
{
#pragma unroll
    for (int j = 0; j < 4; j++) {        // A: 128 rows x 4 16B-chunks
        int idx = tid + j * GTHREADS;
        int row = idx >> 2, ch = idx & 3;
        uint32_t dst = sb + SA + (uint32_t)(row * 80 + ch * 16);
        size_t g = (size_t)(m0 + row) * K + kc + ch * 8;
        cp16(dst, A + g);
    }
#pragma unroll
    for (int j = 0; j < 2; j++) {        // B: 64 rows x 4 chunks
        int idx = tid + j * GTHREADS;
        int row = idx >> 2, ch = idx & 3;
        uint32_t dst = sb + SB + (uint32_t)(row * 80 + ch * 16);
        size_t g = (size_t)(n0 + row) * K + kc + ch * 8;
        cp16(dst, W + g);
    }
}

// ---------------- fp16 GEMM: C = relu(A*W^T + bias) ----------------
__global__ __launch_bounds__(GTHREADS, 4) void gemm_kernel(int layer, int a_sel, int out_sel) {
    const __half *A, *W;
    const float* bias;
    int K;
    if (layer == 0) {
        A = g_x_f; W = g_w0_f;
        bias = g_bias; K = IN_DIM;
    } else {
        A = g_h[a_sel];
        W = g_w_f + (size_t)(layer - 1) * HID * HID;
        bias = g_bias + layer * HID; K = HID;
    }
    __half* C = g_h[out_sel];
    const int NC = K / BK;

    extern __shared__ __align__(128) uint8_t dyn[];
    const uint32_t sbase = (uint32_t)__cvta_generic_to_shared(dyn);

    const int tid  = threadIdx.x;
    const int warp = tid >> 5;
    const int lane = tid & 31;
    const int m0 = blockIdx.y * BM;
    const int n0 = blockIdx.x * BN;
    const int wm0 = (warp & 1) * 64;    // 2 warps along M, tile 64
    const int wn0 = (warp >> 1) * 32;   // 2 warps along N, tile 32

    float acc[4][4][4];
#pragma unroll
    for (int mt = 0; mt < 4; mt++)
#pragma unroll
        for (int nt = 0; nt < 4; nt++)
#pragma unroll
            for (int i = 0; i < 4; i++) acc[mt][nt][i] = 0.f;

    // prologue: chunks 0,1 -> stages 0,1
    load_chunk(sbase,         A, W, K, m0, n0, 0,  tid);
    asm volatile("cp.async.commit_group;" ::: "memory");
    load_chunk(sbase + STAGE, A, W, K, m0, n0, BK, tid);
    asm volatile("cp.async.commit_group;" ::: "memory");

    for (int i = 0; i < NC; i++) {
        if (i + 1 < NC) asm volatile("cp.async.wait_group 1;" ::: "memory");
        else            asm volatile("cp.async.wait_group 0;" ::: "memory");
        __syncthreads();
        if (i + 2 < NC) {
            load_chunk(sbase + (uint32_t)((i + 2) % NSTAGE) * STAGE,
                       A, W, K, m0, n0, (i + 2) * BK, tid);
            asm volatile("cp.async.commit_group;" ::: "memory");
        }

        const uint32_t sb = sbase + (uint32_t)(i % NSTAGE) * STAGE;
#pragma unroll
        for (int kk = 0; kk < BK; kk += 16) {
            uint32_t af[4][4];
            const int rA  = lane & 15;
            const int chA = (kk >> 3) + (lane >> 4);
#pragma unroll
            for (int mt = 0; mt < 4; mt++) {
                uint32_t off = (uint32_t)((wm0 + mt * 16 + rA) * 80 + chA * 16);
                ldsm4(af[mt], sb + SA + off);
            }
            const int rB  = (lane & 7) + ((lane >> 4) << 3);
            const int chB = (kk >> 3) + ((lane >> 3) & 1);
#pragma unroll
            for (int np = 0; np < 2; np++) {
                uint32_t off = (uint32_t)((wn0 + np * 16 + rB) * 80 + chB * 16);
                uint32_t bf[4];
                ldsm4(bf, sb + SB + off);
#pragma unroll
                for (int sub = 0; sub < 2; sub++) {
                    const int nt = np * 2 + sub;
                    const uint32_t b2[2] = { bf[sub * 2], bf[sub * 2 + 1] };
#pragma unroll
                    for (int mt = 0; mt < 4; mt++) {
                        mma_f16(acc[mt][nt], af[mt], b2);
                    }
                }
            }
        }
    }

    // ---- epilogue: bias + relu -> fp16 ----
    const int gid  = lane >> 2;
    const int tid4 = lane & 3;
#pragma unroll
    for (int nt = 0; nt < 4; nt++) {
        const int col = n0 + wn0 + nt * 8 + tid4 * 2;
        const float bz0 = bias[col];
        const float bz1 = bias[col + 1];
#pragma unroll
        for (int mt = 0; mt < 4; mt++) {
            const int rowm = m0 + wm0 + mt * 16 + gid;
            const float* a = acc[mt][nt];
            {
                float v0 = fmaxf(a[0] + bz0, 0.f);
                float v1 = fmaxf(a[1] + bz1, 0.f);
                *reinterpret_cast<__half2*>(C + (size_t)rowm * HID + col) =
                    __halves2half2(__float2half_rn(v0), __float2half_rn(v1));
            }
            {
                float v0 = fmaxf(a[2] + bz0, 0.f);
                float v1 = fmaxf(a[3] + bz1, 0.f);
                *reinterpret_cast<__half2*>(C + (size_t)(rowm + 8) * HID + col) =
                    __halves2half2(__float2half_rn(v0), __float2half_rn(v1));
            }
        }
    }
}

// ---------------- task-gathered multihead ----------------
__global__ __launch_bounds__(128) void head_kernel(int h_sel,
                                                   const int* __restrict__ task32,
                                                   float* __restrict__ out) {
    const int b = blockIdx.x;
    int t = g_task_is64 ? task32[2 * b] : task32[b];
    t = min(max(t, 0), NT - 1);

    const __half* h = g_h[h_sel] + (size_t)b * HID;
    const float* hw = g_hw + (size_t)t * OUTD * HID;

    float acc[OUTD];
#pragma unroll
    for (int o = 0; o < OUTD; o++) acc[o] = 0.f;

    for (int k = threadIdx.x; k < HID; k += blockDim.x) {
        float hv = __half2float(h[k]);
#pragma unroll
        for (int o = 0; o < OUTD; o++) acc[o] = fmaf(hv, hw[(size_t)o * HID + k], acc[o]);
    }

    const int warp = threadIdx.x >> 5;
    const int lane = threadIdx.x & 31;
    __shared__ float red[4][OUTD];
#pragma unroll
    for (int o = 0; o < OUTD; o++) {
        float v = acc[o];
#pragma unroll
        for (int s = 16; s > 0; s >>= 1) v += __shfl_xor_sync(0xffffffffu, v, s);
        if (lane == 0) red[warp][o] = v;
    }
    __syncthreads();
    if (threadIdx.x < OUTD) {
        float s = red[0][threadIdx.x] + red[1][threadIdx.x] +
                  red[2][threadIdx.x] + red[3][threadIdx.x] +
                  g_hb[t * OUTD + threadIdx.x];
        out[(size_t)b * OUTD + threadIdx.x] = s;
    }
}

// ---------------- launch ----------------
extern "C" void kernel_launch(void* const* d_in, const int* in_sizes, int n_in,
                              void* d_out, int out_size) {
    (void)in_sizes; (void)n_in; (void)out_size;
    const float* x      = (const float*)d_in[0];
    const float* mu_w0  = (const float*)d_in[1];
    const float* ls_w0  = (const float*)d_in[2];
    const float* mu_b0  = (const float*)d_in[3];
    const float* ls_b0  = (const float*)d_in[4];
    const float* mu_w   = (const float*)d_in[5];
    const float* ls_w   = (const float*)d_in[6];
    const float* mu_b   = (const float*)d_in[7];
    const float* ls_b   = (const float*)d_in[8];
    const float* mu_hw  = (const float*)d_in[9];
    const float* ls_hw  = (const float*)d_in[10];
    const float* mu_hb  = (const float*)d_in[11];
    const float* ls_hb  = (const float*)d_in[12];
    const float* eps_w0 = (const float*)d_in[13];
    const float* eps_b0 = (const float*)d_in[14];
    const float* eps_w  = (const float*)d_in[15];
    const float* eps_b  = (const float*)d_in[16];
    const float* eps_hw = (const float*)d_in[17];
    const float* eps_hb = (const float*)d_in[18];
    const int* task32   = (const int*)d_in[19];
    float* out = (float*)d_out;

    cudaFuncSetAttribute(gemm_kernel,
                         cudaFuncAttributeMaxDynamicSharedMemorySize, DYN_SMEM);

    // ---- fork: side chain (everything gemm0 does NOT need) ----
    cudaEventRecord(g_ev_fork, 0);
    cudaStreamWaitEvent(g_side_stream, g_ev_fork, 0);

    detect_task_kernel<<<1, 256, 0, g_side_stream>>>(task32);
    {
        int n4 = NEX * HID * HID / 4;
        gen_w4_kernel<<<(n4 + 255) / 256, 256, 0, g_side_stream>>>(
            (const float4*)mu_w, (const float4*)ls_w, (const float4*)eps_w, 1, n4);
    }
    {
        int nr = NEX * HID + NT * OUTD * HID + NT * OUTD;
        gen_rest_kernel<<<(nr + 255) / 256, 256, 0, g_side_stream>>>(
            mu_b, ls_b, eps_b, mu_hw, ls_hw, eps_hw, mu_hb, ls_hb, eps_hb);
    }
    cudaEventRecord(g_ev_join, g_side_stream);

    // ---- main chain: gemm0 prerequisites, then gemm0 (overlaps side) ----
    {
        int n4 = BATCH * IN_DIM / 4;
        quant_x4_kernel<<<(n4 + 255) / 256, 256>>>((const float4*)x, n4);
    }
    {
        int n4 = HID * IN_DIM / 4;
        gen_w4_kernel<<<(n4 + 255) / 256, 256>>>(
            (const float4*)mu_w0, (const float4*)ls_w0, (const float4*)eps_w0, 0, n4);
    }
    gen_bias0_kernel<<<(HID + 255) / 256, 256>>>(mu_b0, ls_b0, eps_b0);

    dim3 grid(HID / BN, BATCH / BM);   // (32, 32) = 1024 CTAs
    gemm_kernel<<<grid, GTHREADS, DYN_SMEM>>>(0, 0, 0);

    // ---- join: layers 1..3 need side-chain outputs ----
    cudaStreamWaitEvent(0, g_ev_join, 0);

    gemm_kernel<<<grid, GTHREADS, DYN_SMEM>>>(1, 0, 1);
    gemm_kernel<<<grid, GTHREADS, DYN_SMEM>>>(2, 1, 0);
    gemm_kernel<<<grid, GTHREADS, DYN_SMEM>>>(3, 0, 1);
    head_kernel<<<BATCH, 128>>>(1, task32, out);
}

// round 14
// speedup vs baseline: 2.9759x; 1.0299x over previous
#include <cuda_runtime.h>
#include <cuda_fp16.h>
#include <cstdint>
#include <cstddef>

#define IN_DIM 1024
#define HID    2048
#define OUTD   10
#define NEX    3
#define NT     10
#define BATCH  4096

// GEMM tiling: 4 CTAs/SM, fine-grained tiles for SM load balance
#define BM      128
#define BN      64
#define BK      32
#define GTHREADS 128
#define SA      0u
#define SB      10240u    // 128*80
#define STAGE   15360u    // + 64*80
#define NSTAGE  3
#define DYN_SMEM (NSTAGE * STAGE)   // 46080 B -> 4 CTAs/SM

// fused pre-gemm0 kernel segment sizes (in float4 units)
#define N4X   (BATCH * IN_DIM / 4)   // 1048576
#define N4W0  (HID * IN_DIM / 4)     // 524288
#define N4B0  (HID / 4)              // 512

// ---------------- static device scratch ----------------
__device__ __align__(256) __half g_x_f[(size_t)BATCH * IN_DIM];
__device__ __align__(256) __half g_w0_f[(size_t)HID * IN_DIM];
__device__ __align__(256) __half g_w_f[(size_t)NEX * HID * HID];
__device__ __align__(256) float  g_bias[HID + NEX * HID];
__device__ __align__(256) __half g_hw[(size_t)NT * OUTD * HID];   // fp16 head weights
__device__ __align__(256) float  g_hb[NT * OUTD];
__device__ __align__(256) __half g_h[2][(size_t)BATCH * HID];
__device__ int g_task_is64;

// ---------------- task dtype detection (validated) ----------------
__global__ void detect_task_kernel(const int* __restrict__ t32) {
    __shared__ int any;
    if (threadIdx.x == 0) any = 0;
    __syncthreads();
    int local = 0;
    for (int i = 1 + 2 * threadIdx.x; i < BATCH; i += 2 * blockDim.x) local |= t32[i];
    if (local) atomicOr(&any, 1);
    __syncthreads();
    if (threadIdx.x == 0) g_task_is64 = (any == 0) ? 1 : 0;
}

// ---------------- helpers ----------------
__device__ __forceinline__ uint2 pack4h(float a, float b, float c, float d) {
    unsigned short q0 = __half_as_ushort(__float2half_rn(a));
    unsigned short q1 = __half_as_ushort(__float2half_rn(b));
    unsigned short q2 = __half_as_ushort(__float2half_rn(c));
    unsigned short q3 = __half_as_ushort(__float2half_rn(d));
    uint2 P;
    P.x = (uint32_t)q0 | ((uint32_t)q1 << 16);
    P.y = (uint32_t)q2 | ((uint32_t)q3 << 16);
    return P;
}

// ---------------- fused pre-gemm0 elementwise: quant_x | gen_w0 | bias0 ----------------
__global__ void fused_pre_kernel(const float4* __restrict__ x,
                                 const float4* __restrict__ mu_w0, const float4* __restrict__ ls_w0,
                                 const float4* __restrict__ eps_w0,
                                 const float4* __restrict__ mu_b0, const float4* __restrict__ ls_b0,
                                 const float4* __restrict__ eps_b0) {
    int i = blockIdx.x * blockDim.x + threadIdx.x;
    if (i < N4X) {
        float4 v = x[i];
        reinterpret_cast<uint2*>(g_x_f)[i] = pack4h(v.x, v.y, v.z, v.w);
    } else if (i < N4X + N4W0) {
        int j = i - N4X;
        float4 m = mu_w0[j], l = ls_w0[j], e = eps_w0[j];
        reinterpret_cast<uint2*>(g_w0_f)[j] = pack4h(
            fmaf(expf(l.x), e.x, m.x), fmaf(expf(l.y), e.y, m.y),
            fmaf(expf(l.z), e.z, m.z), fmaf(expf(l.w), e.w, m.w));
    } else if (i < N4X + N4W0 + N4B0) {
        int j = i - N4X - N4W0;
        float4 m = mu_b0[j], l = ls_b0[j], e = eps_b0[j];
        float4 r;
        r.x = fmaf(expf(l.x), e.x, m.x);
        r.y = fmaf(expf(l.y), e.y, m.y);
        r.z = fmaf(expf(l.z), e.z, m.z);
        r.w = fmaf(expf(l.w), e.w, m.w);
        reinterpret_cast<float4*>(g_bias)[j] = r;
    }
}

// big weight gen (layers 1..3), fp16
__global__ void gen_w4_kernel(const float4* __restrict__ mu,
                              const float4* __restrict__ ls,
                              const float4* __restrict__ eps,
                              int n4) {
    int i = blockIdx.x * blockDim.x + threadIdx.x;
    if (i >= n4) return;
    float4 m = mu[i], l = ls[i], e = eps[i];
    reinterpret_cast<uint2*>(g_w_f)[i] = pack4h(
        fmaf(expf(l.x), e.x, m.x), fmaf(expf(l.y), e.y, m.y),
        fmaf(expf(l.z), e.z, m.z), fmaf(expf(l.w), e.w, m.w));
}

// small gens merged: biases 1..3 (f32), head weights (f16), head biases (f32)
__global__ void gen_rest_kernel(const float* __restrict__ mu_b,  const float* __restrict__ ls_b,  const float* __restrict__ eps_b,
                                const float* __restrict__ mu_hw, const float* __restrict__ ls_hw, const float* __restrict__ eps_hw,
                                const float* __restrict__ mu_hb, const float* __restrict__ ls_hb, const float* __restrict__ eps_hb) {
    const int n1 = NEX * HID;
    const int n2 = NT * OUTD * HID;
    const int n3 = NT * OUTD;
    int i = blockIdx.x * blockDim.x + threadIdx.x;
    if (i < n1) {
        g_bias[HID + i] = fmaf(expf(ls_b[i]), eps_b[i], mu_b[i]);
    } else if (i < n1 + n2) {
        int j = i - n1;
        g_hw[j] = __float2half_rn(fmaf(expf(ls_hw[j]), eps_hw[j], mu_hw[j]));
    } else if (i < n1 + n2 + n3) {
        int j = i - n1 - n2;
        g_hb[j] = fmaf(expf(ls_hb[j]), eps_hb[j], mu_hb[j]);
    }
}

// ---------------- HMMA primitives ----------------
__device__ __forceinline__ void ldsm4(uint32_t d[4], uint32_t addr) {
    asm volatile("ldmatrix.sync.aligned.m8n8.x4.shared.b16 {%0,%1,%2,%3}, [%4];"
                 : "=r"(d[0]), "=r"(d[1]), "=r"(d[2]), "=r"(d[3]) : "r"(addr));
}

__device__ __forceinline__ void mma_f16(float c[4], const uint32_t a[4], const uint32_t b[2]) {
    asm volatile("mma.sync.aligned.m16n8k16.row.col.f32.f16.f16.f32 "
                 "{%0,%1,%2,%3}, {%4,%5,%6,%7}, {%8,%9}, {%0,%1,%2,%3};"
                 : "+f"(c[0]), "+f"(c[1]), "+f"(c[2]), "+f"(c[3])
                 : "r"(a[0]), "r"(a[1]), "r"(a[2]), "r"(a[3]), "r"(b[0]), "r"(b[1]));
}

__device__ __forceinline__ void cp16(uint32_t dst, const void* src) {
    asm volatile("cp.async.cg.shared.global [%0], [%1], 16;" :: "r"(dst), "l"(src) : "memory");
}

// load one BK=32 chunk: A (128x32 fp16) + B (64x32 fp16); 6 cp16/thread
__device__ __forceinline__ void load_chunk(
    uint32_t sb,
    const __half* __restrict__ A, const __half* __restrict__ W,
    int K, int m0, int n0, int kc, int tid)
{
#pragma unroll
    for (int j = 0; j < 4; j++) {        // A: 128 rows x 4 16B-chunks
        int idx = tid + j * GTHREADS;
        int row = idx >> 2, ch = idx & 3;
        uint32_t dst = sb + SA + (uint32_t)(row * 80 + ch * 16);
        size_t g = (size_t)(m0 + row) * K + kc + ch * 8;
        cp16(dst, A + g);
    }
#pragma unroll
    for (int j = 0; j < 2; j++) {        // B: 64 rows x 4 chunks
        int idx = tid + j * GTHREADS;
        int row = idx >> 2, ch = idx & 3;
        uint32_t dst = sb + SB + (uint32_t)(row * 80 + ch * 16);
        size_t g = (size_t)(n0 + row) * K + kc + ch * 8;
        cp16(dst, W + g);
    }
}

// ---------------- fp16 GEMM: C = relu(A*W^T + bias) ----------------
__global__ __launch_bounds__(GTHREADS, 4) void gemm_kernel(int layer, int a_sel, int out_sel) {
    const __half *A, *W;
    const float* bias;
    int K;
    if (layer == 0) {
        A = g_x_f; W = g_w0_f;
        bias = g_bias; K = IN_DIM;
    } else {
        A = g_h[a_sel];
        W = g_w_f + (size_t)(layer - 1) * HID * HID;
        bias = g_bias + layer * HID; K = HID;
    }
    __half* C = g_h[out_sel];
    const int NC = K / BK;

    extern __shared__ __align__(128) uint8_t dyn[];
    const uint32_t sbase = (uint32_t)__cvta_generic_to_shared(dyn);

    const int tid  = threadIdx.x;
    const int warp = tid >> 5;
    const int lane = tid & 31;
    const int m0 = blockIdx.y * BM;
    const int n0 = blockIdx.x * BN;
    const int wm0 = (warp & 1) * 64;    // 2 warps along M, tile 64
    const int wn0 = (warp >> 1) * 32;   // 2 warps along N, tile 32

    float acc[4][4][4];
#pragma unroll
    for (int mt = 0; mt < 4; mt++)
#pragma unroll
        for (int nt = 0; nt < 4; nt++)
#pragma unroll
            for (int i = 0; i < 4; i++) acc[mt][nt][i] = 0.f;

    // prologue: chunks 0,1 -> stages 0,1
    load_chunk(sbase,         A, W, K, m0, n0, 0,  tid);
    asm volatile("cp.async.commit_group;" ::: "memory");
    load_chunk(sbase + STAGE, A, W, K, m0, n0, BK, tid);
    asm volatile("cp.async.commit_group;" ::: "memory");

    for (int i = 0; i < NC; i++) {
        if (i + 1 < NC) asm volatile("cp.async.wait_group 1;" ::: "memory");
        else            asm volatile("cp.async.wait_group 0;" ::: "memory");
        __syncthreads();
        if (i + 2 < NC) {
            load_chunk(sbase + (uint32_t)((i + 2) % NSTAGE) * STAGE,
                       A, W, K, m0, n0, (i + 2) * BK, tid);
            asm volatile("cp.async.commit_group;" ::: "memory");
        }

        const uint32_t sb = sbase + (uint32_t)(i % NSTAGE) * STAGE;
#pragma unroll
        for (int kk = 0; kk < BK; kk += 16) {
            uint32_t af[4][4];
            const int rA  = lane & 15;
            const int chA = (kk >> 3) + (lane >> 4);
#pragma unroll
            for (int mt = 0; mt < 4; mt++) {
                uint32_t off = (uint32_t)((wm0 + mt * 16 + rA) * 80 + chA * 16);
                ldsm4(af[mt], sb + SA + off);
            }
            const int rB  = (lane & 7) + ((lane >> 4) << 3);
            const int chB = (kk >> 3) + ((lane >> 3) & 1);
#pragma unroll
            for (int np = 0; np < 2; np++) {
                uint32_t off = (uint32_t)((wn0 + np * 16 + rB) * 80 + chB * 16);
                uint32_t bf[4];
                ldsm4(bf, sb + SB + off);
#pragma unroll
                for (int sub = 0; sub < 2; sub++) {
                    const int nt = np * 2 + sub;
                    const uint32_t b2[2] = { bf[sub * 2], bf[sub * 2 + 1] };
#pragma unroll
                    for (int mt = 0; mt < 4; mt++) {
                        mma_f16(acc[mt][nt], af[mt], b2);
                    }
                }
            }
        }
    }

    // ---- epilogue: bias + relu -> fp16 ----
    const int gid  = lane >> 2;
    const int tid4 = lane & 3;
#pragma unroll
    for (int nt = 0; nt < 4; nt++) {
        const int col = n0 + wn0 + nt * 8 + tid4 * 2;
        const float bz0 = bias[col];
        const float bz1 = bias[col + 1];
#pragma unroll
        for (int mt = 0; mt < 4; mt++) {
            const int rowm = m0 + wm0 + mt * 16 + gid;
            const float* a = acc[mt][nt];
            {
                float v0 = fmaxf(a[0] + bz0, 0.f);
                float v1 = fmaxf(a[1] + bz1, 0.f);
                *reinterpret_cast<__half2*>(C + (size_t)rowm * HID + col) =
                    __halves2half2(__float2half_rn(v0), __float2half_rn(v1));
            }
            {
                float v0 = fmaxf(a[2] + bz0, 0.f);
                float v1 = fmaxf(a[3] + bz1, 0.f);
                *reinterpret_cast<__half2*>(C + (size_t)(rowm + 8) * HID + col) =
                    __halves2half2(__float2half_rn(v0), __float2half_rn(v1));
            }
        }
    }
}

// ---------------- task-gathered multihead (half2-vectorized) ----------------
__global__ __launch_bounds__(128) void head_kernel(int h_sel,
                                                   const int* __restrict__ task32,
                                                   float* __restrict__ out) {
    const int b = blockIdx.x;
    int t = g_task_is64 ? task32[2 * b] : task32[b];
    t = min(max(t, 0), NT - 1);

    const __half2* h2  = reinterpret_cast<const __half2*>(g_h[h_sel] + (size_t)b * HID);
    const __half2* hw2 = reinterpret_cast<const __half2*>(g_hw + (size_t)t * OUTD * HID);

    float acc[OUTD];
#pragma unroll
    for (int o = 0; o < OUTD; o++) acc[o] = 0.f;

    for (int k2 = threadIdx.x; k2 < HID / 2; k2 += blockDim.x) {
        float2 hv = __half22float2(h2[k2]);
#pragma unroll
        for (int o = 0; o < OUTD; o++) {
            float2 wv = __half22float2(hw2[o * (HID / 2) + k2]);
            acc[o] = fmaf(hv.x, wv.x, fmaf(hv.y, wv.y, acc[o]));
        }
    }

    const int warp = threadIdx.x >> 5;
    const int lane = threadIdx.x & 31;
    __shared__ float red[4][OUTD];
#pragma unroll
    for (int o = 0; o < OUTD; o++) {
        float v = acc[o];
#pragma unroll
        for (int s = 16; s > 0; s >>= 1) v += __shfl_xor_sync(0xffffffffu, v, s);
        if (lane == 0) red[warp][o] = v;
    }
    __syncthreads();
    if (threadIdx.x < OUTD) {
        float s = red[0][threadIdx.x] + red[1][threadIdx.x] +
                  red[2][threadIdx.x] + red[3][threadIdx.x] +
                  g_hb[t * OUTD + threadIdx.x];
        out[(size_t)b * OUTD + threadIdx.x] = s;
    }
}

// ---------------- launch (single stream, no static constructors) ----------------
extern "C" void kernel_launch(void* const* d_in, const int* in_sizes, int n_in,
                              void* d_out, int out_size) {
    (void)in_sizes; (void)n_in; (void)out_size;
    const float* x      = (const float*)d_in[0];
    const float* mu_w0  = (const float*)d_in[1];
    const float* ls_w0  = (const float*)d_in[2];
    const float* mu_b0  = (const float*)d_in[3];
    const float* ls_b0  = (const float*)d_in[4];
    const float* mu_w   = (const float*)d_in[5];
    const float* ls_w   = (const float*)d_in[6];
    const float* mu_b   = (const float*)d_in[7];
    const float* ls_b   = (const float*)d_in[8];
    const float* mu_hw  = (const float*)d_in[9];
    const float* ls_hw  = (const float*)d_in[10];
    const float* mu_hb  = (const float*)d_in[11];
    const float* ls_hb  = (const float*)d_in[12];
    const float* eps_w0 = (const float*)d_in[13];
    const float* eps_b0 = (const float*)d_in[14];
    const float* eps_w  = (const float*)d_in[15];
    const float* eps_b  = (const float*)d_in[16];
    const float* eps_hw = (const float*)d_in[17];
    const float* eps_hb = (const float*)d_in[18];
    const int* task32   = (const int*)d_in[19];
    float* out = (float*)d_out;

    cudaFuncSetAttribute(gemm_kernel,
                         cudaFuncAttributeMaxDynamicSharedMemorySize, DYN_SMEM);

    detect_task_kernel<<<1, 256>>>(task32);

    {
        int ntot = N4X + N4W0 + N4B0;
        fused_pre_kernel<<<(ntot + 255) / 256, 256>>>(
            (const float4*)x,
            (const float4*)mu_w0, (const float4*)ls_w0, (const float4*)eps_w0,
            (const float4*)mu_b0, (const float4*)ls_b0, (const float4*)eps_b0);
    }
    {
        int n4 = NEX * HID * HID / 4;
        gen_w4_kernel<<<(n4 + 255) / 256, 256>>>(
            (const float4*)mu_w, (const float4*)ls_w, (const float4*)eps_w, n4);
    }
    {
        int nr = NEX * HID + NT * OUTD * HID + NT * OUTD;
        gen_rest_kernel<<<(nr + 255) / 256, 256>>>(
            mu_b, ls_b, eps_b, mu_hw, ls_hw, eps_hw, mu_hb, ls_hb, eps_hb);
    }

    dim3 grid(HID / BN, BATCH / BM);   // (32, 32) = 1024 CTAs
    gemm_kernel<<<grid, GTHREADS, DYN_SMEM>>>(0, 0, 0);
    gemm_kernel<<<grid, GTHREADS, DYN_SMEM>>>(1, 0, 1);
    gemm_kernel<<<grid, GTHREADS, DYN_SMEM>>>(2, 1, 0);
    gemm_kernel<<<grid, GTHREADS, DYN_SMEM>>>(3, 0, 1);
    head_kernel<<<BATCH, 128>>>(1, task32, out);
}

// round 15
// speedup vs baseline: 3.0003x; 1.0082x over previous
#include <cuda_runtime.h>
#include <cuda_fp16.h>
#include <cstdint>
#include <cstddef>

#define IN_DIM 1024
#define HID    2048
#define OUTD   10
#define NEX    3
#define NT     10
#define BATCH  4096

// GEMM tiling: 4 CTAs/SM, fine-grained tiles for SM load balance
#define BM      128
#define BN      64
#define BK      32
#define GTHREADS 128
#define SA      0u
#define SB      10240u    // 128*80
#define STAGE   15360u    // + 64*80
#define NSTAGE  3
#define DYN_SMEM (NSTAGE * STAGE)   // 46080 B -> 4 CTAs/SM

// fused pre-gemm0 kernel segment sizes (in float4 units)
#define N4X   (BATCH * IN_DIM / 4)   // 1048576
#define N4W0  (HID * IN_DIM / 4)     // 524288
#define N4B0  (HID / 4)              // 512

// ---------------- static device scratch ----------------
__device__ __align__(256) __half g_x_f[(size_t)BATCH * IN_DIM];
__device__ __align__(256) __half g_w0_f[(size_t)HID * IN_DIM];
__device__ __align__(256) __half g_w_f[(size_t)NEX * HID * HID];
__device__ __align__(256) float  g_bias[HID + NEX * HID];
__device__ __align__(256) __half g_hw[(size_t)NT * OUTD * HID];   // fp16 head weights
__device__ __align__(256) float  g_hb[NT * OUTD];
__device__ __align__(256) __half g_h[2][(size_t)BATCH * HID];
__device__ int g_task_is64;

// ---------------- fork/join stream + events (host-side objects, created once;
// no device memory allocation; this exact pattern passed in round 11) ----------------
static cudaStream_t g_side_stream;
static cudaEvent_t  g_ev_fork, g_ev_join;
static struct SideInit {
    SideInit() {
        cudaStreamCreateWithFlags(&g_side_stream, cudaStreamNonBlocking);
        cudaEventCreateWithFlags(&g_ev_fork, cudaEventDisableTiming);
        cudaEventCreateWithFlags(&g_ev_join, cudaEventDisableTiming);
    }
} g_side_init;

// ---------------- task dtype detection (validated) ----------------
__global__ void detect_task_kernel(const int* __restrict__ t32) {
    __shared__ int any;
    if (threadIdx.x == 0) any = 0;
    __syncthreads();
    int local = 0;
    for (int i = 1 + 2 * threadIdx.x; i < BATCH; i += 2 * blockDim.x) local |= t32[i];
    if (local) atomicOr(&any, 1);
    __syncthreads();
    if (threadIdx.x == 0) g_task_is64 = (any == 0) ? 1 : 0;
}

// ---------------- helpers ----------------
__device__ __forceinline__ uint2 pack4h(float a, float b, float c, float d) {
    unsigned short q0 = __half_as_ushort(__float2half_rn(a));
    unsigned short q1 = __half_as_ushort(__float2half_rn(b));
    unsigned short q2 = __half_as_ushort(__float2half_rn(c));
    unsigned short q3 = __half_as_ushort(__float2half_rn(d));
    uint2 P;
    P.x = (uint32_t)q0 | ((uint32_t)q1 << 16);
    P.y = (uint32_t)q2 | ((uint32_t)q3 << 16);
    return P;
}

// ---------------- fused pre-gemm0 elementwise: quant_x | gen_w0 | bias0 ----------------
__global__ void fused_pre_kernel(const float4* __restrict__ x,
                                 const float4* __restrict__ mu_w0, const float4* __restrict__ ls_w0,
                                 const float4* __restrict__ eps_w0,
                                 const float4* __restrict__ mu_b0, const float4* __restrict__ ls_b0,
                                 const float4* __restrict__ eps_b0) {
    int i = blockIdx.x * blockDim.x + threadIdx.x;
    if (i < N4X) {
        float4 v = x[i];
        reinterpret_cast<uint2*>(g_x_f)[i] = pack4h(v.x, v.y, v.z, v.w);
    } else if (i < N4X + N4W0) {
        int j = i - N4X;
        float4 m = mu_w0[j], l = ls_w0[j], e = eps_w0[j];
        reinterpret_cast<uint2*>(g_w0_f)[j] = pack4h(
            fmaf(expf(l.x), e.x, m.x), fmaf(expf(l.y), e.y, m.y),
            fmaf(expf(l.z), e.z, m.z), fmaf(expf(l.w), e.w, m.w));
    } else if (i < N4X + N4W0 + N4B0) {
        int j = i - N4X - N4W0;
        float4 m = mu_b0[j], l = ls_b0[j], e = eps_b0[j];
        float4 r;
        r.x = fmaf(expf(l.x), e.x, m.x);
        r.y = fmaf(expf(l.y), e.y, m.y);
        r.z = fmaf(expf(l.z), e.z, m.z);
        r.w = fmaf(expf(l.w), e.w, m.w);
        reinterpret_cast<float4*>(g_bias)[j] = r;
    }
}

// big weight gen (layers 1..3), fp16
__global__ void gen_w4_kernel(const float4* __restrict__ mu,
                              const float4* __restrict__ ls,
                              const float4* __restrict__ eps,
                              int n4) {
    int i = blockIdx.x * blockDim.x + threadIdx.x;
    if (i >= n4) return;
    float4 m = mu[i], l = ls[i], e = eps[i];
    reinterpret_cast<uint2*>(g_w_f)[i] = pack4h(
        fmaf(expf(l.x), e.x, m.x), fmaf(expf(l.y), e.y, m.y),
        fmaf(expf(l.z), e.z, m.z), fmaf(expf(l.w), e.w, m.w));
}

// small gens merged: biases 1..3 (f32), head weights (f16), head biases (f32)
__global__ void gen_rest_kernel(const float* __restrict__ mu_b,  const float* __restrict__ ls_b,  const float* __restrict__ eps_b,
                                const float* __restrict__ mu_hw, const float* __restrict__ ls_hw, const float* __restrict__ eps_hw,
                                const float* __restrict__ mu_hb, const float* __restrict__ ls_hb, const float* __restrict__ eps_hb) {
    const int n1 = NEX * HID;
    const int n2 = NT * OUTD * HID;
    const int n3 = NT * OUTD;
    int i = blockIdx.x * blockDim.x + threadIdx.x;
    if (i < n1) {
        g_bias[HID + i] = fmaf(expf(ls_b[i]), eps_b[i], mu_b[i]);
    } else if (i < n1 + n2) {
        int j = i - n1;
        g_hw[j] = __float2half_rn(fmaf(expf(ls_hw[j]), eps_hw[j], mu_hw[j]));
    } else if (i < n1 + n2 + n3) {
        int j = i - n1 - n2;
        g_hb[j] = fmaf(expf(ls_hb[j]), eps_hb[j], mu_hb[j]);
    }
}

// ---------------- HMMA primitives ----------------
__device__ __forceinline__ void ldsm4(uint32_t d[4], uint32_t addr) {
    asm volatile("ldmatrix.sync.aligned.m8n8.x4.shared.b16 {%0,%1,%2,%3}, [%4];"
                 : "=r"(d[0]), "=r"(d[1]), "=r"(d[2]), "=r"(d[3]) : "r"(addr));
}

__device__ __forceinline__ void mma_f16(float c[4], const uint32_t a[4], const uint32_t b[2]) {
    asm volatile("mma.sync.aligned.m16n8k16.row.col.f32.f16.f16.f32 "
                 "{%0,%1,%2,%3}, {%4,%5,%6,%7}, {%8,%9}, {%0,%1,%2,%3};"
                 : "+f"(c[0]), "+f"(c[1]), "+f"(c[2]), "+f"(c[3])
                 : "r"(a[0]), "r"(a[1]), "r"(a[2]), "r"(a[3]), "r"(b[0]), "r"(b[1]));
}

__device__ __forceinline__ void cp16(uint32_t dst, const void* src) {
    asm volatile("cp.async.cg.shared.global [%0], [%1], 16;" :: "r"(dst), "l"(src) : "memory");
}

// load one BK=32 chunk: A (128x32 fp16) + B (64x32 fp16); 6 cp16/thread
__device__ __forceinline__ void load_chunk(
    uint32_t sb,
    const __half* __restrict__ A, const __half* __restrict__ W,
    int K, int m0, int n0, int kc, int tid)
{
#pragma unroll
    for (int j = 0; j < 4; j++) {        // A: 128 rows x 4 16B-chunks
        int idx = tid + j * GTHREADS;
        int row = idx >> 2, ch = idx & 3;
        uint32_t dst = sb + SA + (uint32_t)(row * 80 + ch * 16);
        size_t g = (size_t)(m0 + row) * K + kc + ch * 8;
        cp16(dst, A + g);
    }
#pragma unroll
    for (int j = 0; j < 2; j++) {        // B: 64 rows x 4 chunks
        int idx = tid + j * GTHREADS;
        int row = idx >> 2, ch = idx & 3;
        uint32_t dst = sb + SB + (uint32_t)(row * 80 + ch * 16);
        size_t g = (size_t)(n0 + row) * K + kc + ch * 8;
        cp16(dst, W + g);
    }
}

// ---------------- fp16 GEMM: C = relu(A*W^T + bias) ----------------
__global__ __launch_bounds__(GTHREADS, 4) void gemm_kernel(int layer, int a_sel, int out_sel) {
    const __half *A, *W;
    const float* bias;
    int K;
    if (layer == 0) {
        A = g_x_f; W = g_w0_f;
        bias = g_bias; K = IN_DIM;
    } else {
        A = g_h[a_sel];
        W = g_w_f + (size_t)(layer - 1) * HID * HID;
        bias = g_bias + layer * HID; K = HID;
    }
    __half* C = g_h[out_sel];
    const int NC = K / BK;

    extern __shared__ __align__(128) uint8_t dyn[];
    const uint32_t sbase = (uint32_t)__cvta_generic_to_shared(dyn);

    const int tid  = threadIdx.x;
    const int warp = tid >> 5;
    const int lane = tid & 31;
    const int m0 = blockIdx.y * BM;
    const int n0 = blockIdx.x * BN;
    const int wm0 = (warp & 1) * 64;    // 2 warps along M, tile 64
    const int wn0 = (warp >> 1) * 32;   // 2 warps along N, tile 32

    float acc[4][4][4];
#pragma unroll
    for (int mt = 0; mt < 4; mt++)
#pragma unroll
        for (int nt = 0; nt < 4; nt++)
#pragma unroll
            for (int i = 0; i < 4; i++) acc[mt][nt][i] = 0.f;

    // prologue: chunks 0,1 -> stages 0,1
    load_chunk(sbase,         A, W, K, m0, n0, 0,  tid);
    asm volatile("cp.async.commit_group;" ::: "memory");
    load_chunk(sbase + STAGE, A, W, K, m0, n0, BK, tid);
    asm volatile("cp.async.commit_group;" ::: "memory");

    for (int i = 0; i < NC; i++) {
        if (i + 1 < NC) asm volatile("cp.async.wait_group 1;" ::: "memory");
        else            asm volatile("cp.async.wait_group 0;" ::: "memory");
        __syncthreads();
        if (i + 2 < NC) {
            load_chunk(sbase + (uint32_t)((i + 2) % NSTAGE) * STAGE,
                       A, W, K, m0, n0, (i + 2) * BK, tid);
            asm volatile("cp.async.commit_group;" ::: "memory");
        }

        const uint32_t sb = sbase + (uint32_t)(i % NSTAGE) * STAGE;
#pragma unroll
        for (int kk = 0; kk < BK; kk += 16) {
            uint32_t af[4][4];
            const int rA  = lane & 15;
            const int chA = (kk >> 3) + (lane >> 4);
#pragma unroll
            for (int mt = 0; mt < 4; mt++) {
                uint32_t off = (uint32_t)((wm0 + mt * 16 + rA) * 80 + chA * 16);
                ldsm4(af[mt], sb + SA + off);
            }
            const int rB  = (lane & 7) + ((lane >> 4) << 3);
            const int chB = (kk >> 3) + ((lane >> 3) & 1);
#pragma unroll
            for (int np = 0; np < 2; np++) {
                uint32_t off = (uint32_t)((wn0 + np * 16 + rB) * 80 + chB * 16);
                uint32_t bf[4];
                ldsm4(bf, sb + SB + off);
#pragma unroll
                for (int sub = 0; sub < 2; sub++) {
                    const int nt = np * 2 + sub;
                    const uint32_t b2[2] = { bf[sub * 2], bf[sub * 2 + 1] };
#pragma unroll
                    for (int mt = 0; mt < 4; mt++) {
                        mma_f16(acc[mt][nt], af[mt], b2);
                    }
                }
            }
        }
    }

    // ---- epilogue: bias + relu -> fp16 ----
    const int gid  = lane >> 2;
    const int tid4 = lane & 3;
#pragma unroll
    for (int nt = 0; nt < 4; nt++) {
        const int col = n0 + wn0 + nt * 8 + tid4 * 2;
        const float bz0 = bias[col];
        const float bz1 = bias[col + 1];
#pragma unroll
        for (int mt = 0; mt < 4; mt++) {
            const int rowm = m0 + wm0 + mt * 16 + gid;
            const float* a = acc[mt][nt];
            {
                float v0 = fmaxf(a[0] + bz0, 0.f);
                float v1 = fmaxf(a[1] + bz1, 0.f);
                *reinterpret_cast<__half2*>(C + (size_t)rowm * HID + col) =
                    __halves2half2(__float2half_rn(v0), __float2half_rn(v1));
            }
            {
                float v0 = fmaxf(a[2] + bz0, 0.f);
                float v1 = fmaxf(a[3] + bz1, 0.f);
                *reinterpret_cast<__half2*>(C + (size_t)(rowm + 8) * HID + col) =
                    __halves2half2(__float2half_rn(v0), __float2half_rn(v1));
            }
        }
    }
}

// ---------------- task-gathered multihead (half2-vectorized) ----------------
__global__ __launch_bounds__(128) void head_kernel(int h_sel,
                                                   const int* __restrict__ task32,
                                                   float* __restrict__ out) {
    const int b = blockIdx.x;
    int t = g_task_is64 ? task32[2 * b] : task32[b];
    t = min(max(t, 0), NT - 1);

    const __half2* h2  = reinterpret_cast<const __half2*>(g_h[h_sel] + (size_t)b * HID);
    const __half2* hw2 = reinterpret_cast<const __half2*>(g_hw + (size_t)t * OUTD * HID);

    float acc[OUTD];
#pragma unroll
    for (int o = 0; o < OUTD; o++) acc[o] = 0.f;

    for (int k2 = threadIdx.x; k2 < HID / 2; k2 += blockDim.x) {
        float2 hv = __half22float2(h2[k2]);
#pragma unroll
        for (int o = 0; o < OUTD; o++) {
            float2 wv = __half22float2(hw2[o * (HID / 2) + k2]);
            acc[o] = fmaf(hv.x, wv.x, fmaf(hv.y, wv.y, acc[o]));
        }
    }

    const int warp = threadIdx.x >> 5;
    const int lane = threadIdx.x & 31;
    __shared__ float red[4][OUTD];
#pragma unroll
    for (int o = 0; o < OUTD; o++) {
        float v = acc[o];
#pragma unroll
        for (int s = 16; s > 0; s >>= 1) v += __shfl_xor_sync(0xffffffffu, v, s);
        if (lane == 0) red[warp][o] = v;
    }
    __syncthreads();
    if (threadIdx.x < OUTD) {
        float s = red[0][threadIdx.x] + red[1][threadIdx.x] +
                  red[2][threadIdx.x] + red[3][threadIdx.x] +
                  g_hb[t * OUTD + threadIdx.x];
        out[(size_t)b * OUTD + threadIdx.x] = s;
    }
}

// ---------------- launch ----------------
extern "C" void kernel_launch(void* const* d_in, const int* in_sizes, int n_in,
                              void* d_out, int out_size) {
    (void)in_sizes; (void)n_in; (void)out_size;
    const float* x      = (const float*)d_in[0];
    const float* mu_w0  = (const float*)d_in[1];
    const float* ls_w0  = (const float*)d_in[2];
    const float* mu_b0  = (const float*)d_in[3];
    const float* ls_b0  = (const float*)d_in[4];
    const float* mu_w   = (const float*)d_in[5];
    const float* ls_w   = (const float*)d_in[6];
    const float* mu_b   = (const float*)d_in[7];
    const float* ls_b   = (const float*)d_in[8];
    const float* mu_hw  = (const float*)d_in[9];
    const float* ls_hw  = (const float*)d_in[10];
    const float* mu_hb  = (const float*)d_in[11];
    const float* ls_hb  = (const float*)d_in[12];
    const float* eps_w0 = (const float*)d_in[13];
    const float* eps_b0 = (const float*)d_in[14];
    const float* eps_w  = (const float*)d_in[15];
    const float* eps_b  = (const float*)d_in[16];
    const float* eps_hw = (const float*)d_in[17];
    const float* eps_hb = (const float*)d_in[18];
    const int* task32   = (const int*)d_in[19];
    float* out = (float*)d_out;

    cudaFuncSetAttribute(gemm_kernel,
                         cudaFuncAttributeMaxDynamicSharedMemorySize, DYN_SMEM);

    // ---- fork: side chain (everything gemm0 does NOT need) ----
    cudaEventRecord(g_ev_fork, 0);
    cudaStreamWaitEvent(g_side_stream, g_ev_fork, 0);

    detect_task_kernel<<<1, 256, 0, g_side_stream>>>(task32);
    {
        int n4 = NEX * HID * HID / 4;
        gen_w4_kernel<<<(n4 + 255) / 256, 256, 0, g_side_stream>>>(
            (const float4*)mu_w, (const float4*)ls_w, (const float4*)eps_w, n4);
    }
    {
        int nr = NEX * HID + NT * OUTD * HID + NT * OUTD;
        gen_rest_kernel<<<(nr + 255) / 256, 256, 0, g_side_stream>>>(
            mu_b, ls_b, eps_b, mu_hw, ls_hw, eps_hw, mu_hb, ls_hb, eps_hb);
    }
    cudaEventRecord(g_ev_join, g_side_stream);

    // ---- main chain: fused gemm0 prerequisites, then gemm0 (overlaps side) ----
    {
        int ntot = N4X + N4W0 + N4B0;
        fused_pre_kernel<<<(ntot + 255) / 256, 256>>>(
            (const float4*)x,
            (const float4*)mu_w0, (const float4*)ls_w0, (const float4*)eps_w0,
            (const float4*)mu_b0, (const float4*)ls_b0, (const float4*)eps_b0);
    }

    dim3 grid(HID / BN, BATCH / BM);   // (32, 32) = 1024 CTAs
    gemm_kernel<<<grid, GTHREADS, DYN_SMEM>>>(0, 0, 0);

    // ---- join: layers 1..3 need side-chain outputs ----
    cudaStreamWaitEvent(0, g_ev_join, 0);

    gemm_kernel<<<grid, GTHREADS, DYN_SMEM>>>(1, 0, 1);
    gemm_kernel<<<grid, GTHREADS, DYN_SMEM>>>(2, 1, 0);
    gemm_kernel<<<grid, GTHREADS, DYN_SMEM>>>(3, 0, 1);
    head_kernel<<<BATCH, 128>>>(1, task32, out);
}

// round 16
// speedup vs baseline: 3.0086x; 1.0027x over previous
#include <cuda_runtime.h>
#include <cuda_fp16.h>
#include <cstdint>
#include <cstddef>

#define IN_DIM 1024
#define HID    2048
#define OUTD   10
#define NEX    3
#define NT     10
#define BATCH  4096

// GEMM tiling: 4 CTAs/SM, fine-grained tiles for SM load balance
#define BM      128
#define BN      64
#define BK      32
#define GTHREADS 128
#define SA      0u
#define SB      10240u    // 128*80
#define STAGE   15360u    // + 64*80
#define NSTAGE  3
#define DYN_SMEM (NSTAGE * STAGE)   // 46080 B -> 4 CTAs/SM

// fused pre-gemm0 kernel segment sizes (in float4 units)
#define N4X   (BATCH * IN_DIM / 4)   // 1048576
#define N4W0  (HID * IN_DIM / 4)     // 524288
#define N4B0  (HID / 4)              // 512
#define N4W   (HID * HID / 4)        // per-layer W gen size

// ---------------- static device scratch ----------------
__device__ __align__(256) __half g_x_f[(size_t)BATCH * IN_DIM];
__device__ __align__(256) __half g_w0_f[(size_t)HID * IN_DIM];
__device__ __align__(256) __half g_w_f[(size_t)NEX * HID * HID];
__device__ __align__(256) float  g_bias[HID + NEX * HID];
__device__ __align__(256) __half g_hw[(size_t)NT * OUTD * HID];   // fp16 head weights
__device__ __align__(256) float  g_hb[NT * OUTD];
__device__ __align__(256) __half g_h[2][(size_t)BATCH * HID];
__device__ int g_task_is64;

// ---------------- fork/join stream + events (host-side objects, created once;
// no device memory allocation; pattern validated rounds 11/15) ----------------
static cudaStream_t g_side_stream;
static cudaEvent_t  g_ev_fork, g_ev_j1, g_ev_j2, g_ev_j3;
static struct SideInit {
    SideInit() {
        int lo = 0, hi = 0;
        cudaDeviceGetStreamPriorityRange(&lo, &hi);   // hi = highest priority
        cudaStreamCreateWithPriority(&g_side_stream, cudaStreamNonBlocking, hi);
        cudaEventCreateWithFlags(&g_ev_fork, cudaEventDisableTiming);
        cudaEventCreateWithFlags(&g_ev_j1, cudaEventDisableTiming);
        cudaEventCreateWithFlags(&g_ev_j2, cudaEventDisableTiming);
        cudaEventCreateWithFlags(&g_ev_j3, cudaEventDisableTiming);
    }
} g_side_init;

// ---------------- task dtype detection (validated) ----------------
__global__ void detect_task_kernel(const int* __restrict__ t32) {
    __shared__ int any;
    if (threadIdx.x == 0) any = 0;
    __syncthreads();
    int local = 0;
    for (int i = 1 + 2 * threadIdx.x; i < BATCH; i += 2 * blockDim.x) local |= t32[i];
    if (local) atomicOr(&any, 1);
    __syncthreads();
    if (threadIdx.x == 0) g_task_is64 = (any == 0) ? 1 : 0;
}

// ---------------- helpers ----------------
__device__ __forceinline__ uint2 pack4h(float a, float b, float c, float d) {
    unsigned short q0 = __half_as_ushort(__float2half_rn(a));
    unsigned short q1 = __half_as_ushort(__float2half_rn(b));
    unsigned short q2 = __half_as_ushort(__float2half_rn(c));
    unsigned short q3 = __half_as_ushort(__float2half_rn(d));
    uint2 P;
    P.x = (uint32_t)q0 | ((uint32_t)q1 << 16);
    P.y = (uint32_t)q2 | ((uint32_t)q3 << 16);
    return P;
}

// ---------------- fused pre-gemm0 elementwise: quant_x | gen_w0 | bias0 ----------------
__global__ void fused_pre_kernel(const float4* __restrict__ x,
                                 const float4* __restrict__ mu_w0, const float4* __restrict__ ls_w0,
                                 const float4* __restrict__ eps_w0,
                                 const float4* __restrict__ mu_b0, const float4* __restrict__ ls_b0,
                                 const float4* __restrict__ eps_b0) {
    int i = blockIdx.x * blockDim.x + threadIdx.x;
    if (i < N4X) {
        float4 v = x[i];
        reinterpret_cast<uint2*>(g_x_f)[i] = pack4h(v.x, v.y, v.z, v.w);
    } else if (i < N4X + N4W0) {
        int j = i - N4X;
        float4 m = mu_w0[j], l = ls_w0[j], e = eps_w0[j];
        reinterpret_cast<uint2*>(g_w0_f)[j] = pack4h(
            fmaf(expf(l.x), e.x, m.x), fmaf(expf(l.y), e.y, m.y),
            fmaf(expf(l.z), e.z, m.z), fmaf(expf(l.w), e.w, m.w));
    } else if (i < N4X + N4W0 + N4B0) {
        int j = i - N4X - N4W0;
        float4 m = mu_b0[j], l = ls_b0[j], e = eps_b0[j];
        float4 r;
        r.x = fmaf(expf(l.x), e.x, m.x);
        r.y = fmaf(expf(l.y), e.y, m.y);
        r.z = fmaf(expf(l.z), e.z, m.z);
        r.w = fmaf(expf(l.w), e.w, m.w);
        reinterpret_cast<float4*>(g_bias)[j] = r;
    }
}

// per-layer weight gen (fp16); off4 = float4 offset into g_w_f
__global__ void gen_w4_kernel(const float4* __restrict__ mu,
                              const float4* __restrict__ ls,
                              const float4* __restrict__ eps,
                              int off4) {
    int i = blockIdx.x * blockDim.x + threadIdx.x;
    if (i >= N4W) return;
    float4 m = mu[i], l = ls[i], e = eps[i];
    reinterpret_cast<uint2*>(g_w_f)[off4 + i] = pack4h(
        fmaf(expf(l.x), e.x, m.x), fmaf(expf(l.y), e.y, m.y),
        fmaf(expf(l.z), e.z, m.z), fmaf(expf(l.w), e.w, m.w));
}

// small gens merged: biases 1..3 (f32), head weights (f16), head biases (f32)
__global__ void gen_rest_kernel(const float* __restrict__ mu_b,  const float* __restrict__ ls_b,  const float* __restrict__ eps_b,
                                const float* __restrict__ mu_hw, const float* __restrict__ ls_hw, const float* __restrict__ eps_hw,
                                const float* __restrict__ mu_hb, const float* __restrict__ ls_hb, const float* __restrict__ eps_hb) {
    const int n1 = NEX * HID;
    const int n2 = NT * OUTD * HID;
    const int n3 = NT * OUTD;
    int i = blockIdx.x * blockDim.x + threadIdx.x;
    if (i < n1) {
        g_bias[HID + i] = fmaf(expf(ls_b[i]), eps_b[i], mu_b[i]);
    } else if (i < n1 + n2) {
        int j = i - n1;
        g_hw[j] = __float2half_rn(fmaf(expf(ls_hw[j]), eps_hw[j], mu_hw[j]));
    } else if (i < n1 + n2 + n3) {
        int j = i - n1 - n2;
        g_hb[j] = fmaf(expf(ls_hb[j]), eps_hb[j], mu_hb[j]);
    }
}

// ---------------- HMMA primitives ----------------
__device__ __forceinline__ void ldsm4(uint32_t d[4], uint32_t addr) {
    asm volatile("ldmatrix.sync.aligned.m8n8.x4.shared.b16 {%0,%1,%2,%3}, [%4];"
                 : "=r"(d[0]), "=r"(d[1]), "=r"(d[2]), "=r"(d[3]) : "r"(addr));
}

__device__ __forceinline__ void mma_f16(float c[4], const uint32_t a[4], const uint32_t b[2]) {
    asm volatile("mma.sync.aligned.m16n8k16.row.col.f32.f16.f16.f32 "
                 "{%0,%1,%2,%3}, {%4,%5,%6,%7}, {%8,%9}, {%0,%1,%2,%3};"
                 : "+f"(c[0]), "+f"(c[1]), "+f"(c[2]), "+f"(c[3])
                 : "r"(a[0]), "r"(a[1]), "r"(a[2]), "r"(a[3]), "r"(b[0]), "r"(b[1]));
}

__device__ __forceinline__ void cp16(uint32_t dst, const void* src) {
    asm volatile("cp.async.cg.shared.global [%0], [%1], 16;" :: "r"(dst), "l"(src) : "memory");
}

// load one BK=32 chunk: A (128x32 fp16) + B (64x32 fp16); 6 cp16/thread
__device__ __forceinline__ void load_chunk(
    uint32_t sb,
    const __half* __restrict__ A, const __half* __restrict__ W,
    int K, int m0, int n0, int kc, int tid)
{
#pragma unroll
    for (int j = 0; j < 4; j++) {        // A: 128 rows x 4 16B-chunks
        int idx = tid + j * GTHREADS;
        int row = idx >> 2, ch = idx & 3;
        uint32_t dst = sb + SA + (uint32_t)(row * 80 + ch * 16);
        size_t g = (size_t)(m0 + row) * K + kc + ch * 8;
        cp16(dst, A + g);
    }
#pragma unroll
    for (int j = 0; j < 2; j++) {        // B: 64 rows x 4 chunks
        int idx = tid + j * GTHREADS;
        int row = idx >> 2, ch = idx & 3;
        uint32_t dst = sb + SB + (uint32_t)(row * 80 + ch * 16);
        size_t g = (size_t)(n0 + row) * K + kc + ch * 8;
        cp16(dst, W + g);
    }
}

// ---------------- fp16 GEMM: C = relu(A*W^T + bias) ----------------
__global__ __launch_bounds__(GTHREADS, 4) void gemm_kernel(int layer, int a_sel, int out_sel) {
    const __half *A, *W;
    const float* bias;
    int K;
    if (layer == 0) {
        A = g_x_f; W = g_w0_f;
        bias = g_bias; K = IN_DIM;
    } else {
        A = g_h[a_sel];
        W = g_w_f + (size_t)(layer - 1) * HID * HID;
        bias = g_bias + layer * HID; K = HID;
    }
    __half* C = g_h[out_sel];
    const int NC = K / BK;

    extern __shared__ __align__(128) uint8_t dyn[];
    const uint32_t sbase = (uint32_t)__cvta_generic_to_shared(dyn);

    const int tid  = threadIdx.x;
    const int warp = tid >> 5;
    const int lane = tid & 31;
    const int m0 = blockIdx.y * BM;
    const int n0 = blockIdx.x * BN;
    const int wm0 = (warp & 1) * 64;    // 2 warps along M, tile 64
    const int wn0 = (warp >> 1) * 32;   // 2 warps along N, tile 32

    float acc[4][4][4];
#pragma unroll
    for (int mt = 0; mt < 4; mt++)
#pragma unroll
        for (int nt = 0; nt < 4; nt++)
#pragma unroll
            for (int i = 0; i < 4; i++) acc[mt][nt][i] = 0.f;

    // prologue: chunks 0,1 -> stages 0,1
    load_chunk(sbase,         A, W, K, m0, n0, 0,  tid);
    asm volatile("cp.async.commit_group;" ::: "memory");
    load_chunk(sbase + STAGE, A, W, K, m0, n0, BK, tid);
    asm volatile("cp.async.commit_group;" ::: "memory");

    for (int i = 0; i < NC; i++) {
        if (i + 1 < NC) asm volatile("cp.async.wait_group 1;" ::: "memory");
        else            asm volatile("cp.async.wait_group 0;" ::: "memory");
        __syncthreads();
        if (i + 2 < NC) {
            load_chunk(sbase + (uint32_t)((i + 2) % NSTAGE) * STAGE,
                       A, W, K, m0, n0, (i + 2) * BK, tid);
            asm volatile("cp.async.commit_group;" ::: "memory");
        }

        const uint32_t sb = sbase + (uint32_t)(i % NSTAGE) * STAGE;
#pragma unroll
        for (int kk = 0; kk < BK; kk += 16) {
            uint32_t af[4][4];
            const int rA  = lane & 15;
            const int chA = (kk >> 3) + (lane >> 4);
#pragma unroll
            for (int mt = 0; mt < 4; mt++) {
                uint32_t off = (uint32_t)((wm0 + mt * 16 + rA) * 80 + chA * 16);
                ldsm4(af[mt], sb + SA + off);
            }
            const int rB  = (lane & 7) + ((lane >> 4) << 3);
            const int chB = (kk >> 3) + ((lane >> 3) & 1);
#pragma unroll
            for (int np = 0; np < 2; np++) {
                uint32_t off = (uint32_t)((wn0 + np * 16 + rB) * 80 + chB * 16);
                uint32_t bf[4];
                ldsm4(bf, sb + SB + off);
#pragma unroll
                for (int sub = 0; sub < 2; sub++) {
                    const int nt = np * 2 + sub;
                    const uint32_t b2[2] = { bf[sub * 2], bf[sub * 2 + 1] };
#pragma unroll
                    for (int mt = 0; mt < 4; mt++) {
                        mma_f16(acc[mt][nt], af[mt], b2);
                    }
                }
            }
        }
    }

    // ---- epilogue: bias + relu -> fp16 ----
    const int gid  = lane >> 2;
    const int tid4 = lane & 3;
#pragma unroll
    for (int nt = 0; nt < 4; nt++) {
        const int col = n0 + wn0 + nt * 8 + tid4 * 2;
        const float bz0 = bias[col];
        const float bz1 = bias[col + 1];
#pragma unroll
        for (int mt = 0; mt < 4; mt++) {
            const int rowm = m0 + wm0 + mt * 16 + gid;
            const float* a = acc[mt][nt];
            {
                float v0 = fmaxf(a[0] + bz0, 0.f);
                float v1 = fmaxf(a[1] + bz1, 0.f);
                *reinterpret_cast<__half2*>(C + (size_t)rowm * HID + col) =
                    __halves2half2(__float2half_rn(v0), __float2half_rn(v1));
            }
            {
                float v0 = fmaxf(a[2] + bz0, 0.f);
                float v1 = fmaxf(a[3] + bz1, 0.f);
                *reinterpret_cast<__half2*>(C + (size_t)(rowm + 8) * HID + col) =
                    __halves2half2(__float2half_rn(v0), __float2half_rn(v1));
            }
        }
    }
}

// ---------------- task-gathered multihead (half2-vectorized) ----------------
__global__ __launch_bounds__(128) void head_kernel(int h_sel,
                                                   const int* __restrict__ task32,
                                                   float* __restrict__ out) {
    const int b = blockIdx.x;
    int t = g_task_is64 ? task32[2 * b] : task32[b];
    t = min(max(t, 0), NT - 1);

    const __half2* h2  = reinterpret_cast<const __half2*>(g_h[h_sel] + (size_t)b * HID);
    const __half2* hw2 = reinterpret_cast<const __half2*>(g_hw + (size_t)t * OUTD * HID);

    float acc[OUTD];
#pragma unroll
    for (int o = 0; o < OUTD; o++) acc[o] = 0.f;

    for (int k2 = threadIdx.x; k2 < HID / 2; k2 += blockDim.x) {
        float2 hv = __half22float2(h2[k2]);
#pragma unroll
        for (int o = 0; o < OUTD; o++) {
            float2 wv = __half22float2(hw2[o * (HID / 2) + k2]);
            acc[o] = fmaf(hv.x, wv.x, fmaf(hv.y, wv.y, acc[o]));
        }
    }

    const int warp = threadIdx.x >> 5;
    const int lane = threadIdx.x & 31;
    __shared__ float red[4][OUTD];
#pragma unroll
    for (int o = 0; o < OUTD; o++) {
        float v = acc[o];
#pragma unroll
        for (int s = 16; s > 0; s >>= 1) v += __shfl_xor_sync(0xffffffffu, v, s);
        if (lane == 0) red[warp][o] = v;
    }
    __syncthreads();
    if (threadIdx.x < OUTD) {
        float s = red[0][threadIdx.x] + red[1][threadIdx.x] +
                  red[2][threadIdx.x] + red[3][threadIdx.x] +
                  g_hb[t * OUTD + threadIdx.x];
        out[(size_t)b * OUTD + threadIdx.x] = s;
    }
}

// ---------------- launch ----------------
extern "C" void kernel_launch(void* const* d_in, const int* in_sizes, int n_in,
                              void* d_out, int out_size) {
    (void)in_sizes; (void)n_in; (void)out_size;
    const float* x      = (const float*)d_in[0];
    const float* mu_w0  = (const float*)d_in[1];
    const float* ls_w0  = (const float*)d_in[2];
    const float* mu_b0  = (const float*)d_in[3];
    const float* ls_b0  = (const float*)d_in[4];
    const float* mu_w   = (const float*)d_in[5];
    const float* ls_w   = (const float*)d_in[6];
    const float* mu_b   = (const float*)d_in[7];
    const float* ls_b   = (const float*)d_in[8];
    const float* mu_hw  = (const float*)d_in[9];
    const float* ls_hw  = (const float*)d_in[10];
    const float* mu_hb  = (const float*)d_in[11];
    const float* ls_hb  = (const float*)d_in[12];
    const float* eps_w0 = (const float*)d_in[13];
    const float* eps_b0 = (const float*)d_in[14];
    const float* eps_w  = (const float*)d_in[15];
    const float* eps_b  = (const float*)d_in[16];
    const float* eps_hw = (const float*)d_in[17];
    const float* eps_hb = (const float*)d_in[18];
    const int* task32   = (const int*)d_in[19];
    float* out = (float*)d_out;

    cudaFuncSetAttribute(gemm_kernel,
                         cudaFuncAttributeMaxDynamicSharedMemorySize, DYN_SMEM);

    const int nblk_w = (N4W + 255) / 256;

    // ---- fork: side chain with per-layer completion events ----
    cudaEventRecord(g_ev_fork, 0);
    cudaStreamWaitEvent(g_side_stream, g_ev_fork, 0);

    detect_task_kernel<<<1, 256, 0, g_side_stream>>>(task32);
    {
        int nr = NEX * HID + NT * OUTD * HID + NT * OUTD;
        gen_rest_kernel<<<(nr + 255) / 256, 256, 0, g_side_stream>>>(
            mu_b, ls_b, eps_b, mu_hw, ls_hw, eps_hw, mu_hb, ls_hb, eps_hb);
    }
    gen_w4_kernel<<<nblk_w, 256, 0, g_side_stream>>>(
        (const float4*)mu_w, (const float4*)ls_w, (const float4*)eps_w, 0);
    cudaEventRecord(g_ev_j1, g_side_stream);
    gen_w4_kernel<<<nblk_w, 256, 0, g_side_stream>>>(
        (const float4*)(mu_w)  + N4W, (const float4*)(ls_w)  + N4W,
        (const float4*)(eps_w) + N4W, N4W);
    cudaEventRecord(g_ev_j2, g_side_stream);
    gen_w4_kernel<<<nblk_w, 256, 0, g_side_stream>>>(
        (const float4*)(mu_w)  + 2 * N4W, (const float4*)(ls_w)  + 2 * N4W,
        (const float4*)(eps_w) + 2 * N4W, 2 * N4W);
    cudaEventRecord(g_ev_j3, g_side_stream);

    // ---- main chain ----
    {
        int ntot = N4X + N4W0 + N4B0;
        fused_pre_kernel<<<(ntot + 255) / 256, 256>>>(
            (const float4*)x,
            (const float4*)mu_w0, (const float4*)ls_w0, (const float4*)eps_w0,
            (const float4*)mu_b0, (const float4*)ls_b0, (const float4*)eps_b0);
    }

    dim3 grid(HID / BN, BATCH / BM);   // (32, 32) = 1024 CTAs
    gemm_kernel<<<grid, GTHREADS, DYN_SMEM>>>(0, 0, 0);

    cudaStreamWaitEvent(0, g_ev_j1, 0);
    gemm_kernel<<<grid, GTHREADS, DYN_SMEM>>>(1, 0, 1);
    cudaStreamWaitEvent(0, g_ev_j2, 0);
    gemm_kernel<<<grid, GTHREADS, DYN_SMEM>>>(2, 1, 0);
    cudaStreamWaitEvent(0, g_ev_j3, 0);
    gemm_kernel<<<grid, GTHREADS, DYN_SMEM>>>(3, 0, 1);
    head_kernel<<<BATCH, 128>>>(1, task32, out);
}

// round 17
// speedup vs baseline: 3.4116x; 1.1340x over previous
#include <cuda_runtime.h>
#include <cuda_fp16.h>
#include <cstdint>
#include <cstddef>

#define IN_DIM 1024
#define HID    2048
#define OUTD   10
#define NEX    3
#define NT     10
#define BATCH  4096

// GEMM tiling: 4 CTAs/SM, BK=64 double-buffered (fewer syncs per layer)
#define BM      128
#define BN      64
#define BK      64
#define GTHREADS 128
#define PADB    144       // smem row stride bytes (9*16: 16B-aligned, ldsm conflict-free)
#define SA      0u
#define SB      18432u    // 128*144
#define STAGE   27648u    // + 64*144
#define NSTAGE  2
#define DYN_SMEM (NSTAGE * STAGE)   // 55296 B -> 4 CTAs/SM (221184 <= 228KB)

// fused pre-gemm0 kernel segment sizes (in float4 units)
#define N4X   (BATCH * IN_DIM / 4)   // 1048576
#define N4W0  (HID * IN_DIM / 4)     // 524288
#define N4B0  (HID / 4)              // 512
#define N4W   (HID * HID / 4)        // per-layer W gen size

// ---------------- static device scratch ----------------
__device__ __align__(256) __half g_x_f[(size_t)BATCH * IN_DIM];
__device__ __align__(256) __half g_w0_f[(size_t)HID * IN_DIM];
__device__ __align__(256) __half g_w_f[(size_t)NEX * HID * HID];
__device__ __align__(256) float  g_bias[HID + NEX * HID];
__device__ __align__(256) __half g_hw[(size_t)NT * OUTD * HID];   // fp16 head weights
__device__ __align__(256) float  g_hb[NT * OUTD];
__device__ __align__(256) __half g_h[2][(size_t)BATCH * HID];
__device__ int g_task_is64;

// ---------------- fork/join stream + events (validated rounds 11/15/16) ----------------
static cudaStream_t g_side_stream;
static cudaEvent_t  g_ev_fork, g_ev_j1, g_ev_j2, g_ev_j3;
static struct SideInit {
    SideInit() {
        int lo = 0, hi = 0;
        cudaDeviceGetStreamPriorityRange(&lo, &hi);
        cudaStreamCreateWithPriority(&g_side_stream, cudaStreamNonBlocking, hi);
        cudaEventCreateWithFlags(&g_ev_fork, cudaEventDisableTiming);
        cudaEventCreateWithFlags(&g_ev_j1, cudaEventDisableTiming);
        cudaEventCreateWithFlags(&g_ev_j2, cudaEventDisableTiming);
        cudaEventCreateWithFlags(&g_ev_j3, cudaEventDisableTiming);
    }
} g_side_init;

// ---------------- task dtype detection (validated) ----------------
__global__ void detect_task_kernel(const int* __restrict__ t32) {
    __shared__ int any;
    if (threadIdx.x == 0) any = 0;
    __syncthreads();
    int local = 0;
    for (int i = 1 + 2 * threadIdx.x; i < BATCH; i += 2 * blockDim.x) local |= t32[i];
    if (local) atomicOr(&any, 1);
    __syncthreads();
    if (threadIdx.x == 0) g_task_is64 = (any == 0) ? 1 : 0;
}

// ---------------- helpers ----------------
__device__ __forceinline__ uint2 pack4h(float a, float b, float c, float d) {
    unsigned short q0 = __half_as_ushort(__float2half_rn(a));
    unsigned short q1 = __half_as_ushort(__float2half_rn(b));
    unsigned short q2 = __half_as_ushort(__float2half_rn(c));
    unsigned short q3 = __half_as_ushort(__float2half_rn(d));
    uint2 P;
    P.x = (uint32_t)q0 | ((uint32_t)q1 << 16);
    P.y = (uint32_t)q2 | ((uint32_t)q3 << 16);
    return P;
}

// ---------------- fused pre-gemm0 elementwise: quant_x | gen_w0 | bias0 ----------------
__global__ void fused_pre_kernel(const float4* __restrict__ x,
                                 const float4* __restrict__ mu_w0, const float4* __restrict__ ls_w0,
                                 const float4* __restrict__ eps_w0,
                                 const float4* __restrict__ mu_b0, const float4* __restrict__ ls_b0,
                                 const float4* __restrict__ eps_b0) {
    int i = blockIdx.x * blockDim.x + threadIdx.x;
    if (i < N4X) {
        float4 v = x[i];
        reinterpret_cast<uint2*>(g_x_f)[i] = pack4h(v.x, v.y, v.z, v.w);
    } else if (i < N4X + N4W0) {
        int j = i - N4X;
        float4 m = mu_w0[j], l = ls_w0[j], e = eps_w0[j];
        reinterpret_cast<uint2*>(g_w0_f)[j] = pack4h(
            fmaf(expf(l.x), e.x, m.x), fmaf(expf(l.y), e.y, m.y),
            fmaf(expf(l.z), e.z, m.z), fmaf(expf(l.w), e.w, m.w));
    } else if (i < N4X + N4W0 + N4B0) {
        int j = i - N4X - N4W0;
        float4 m = mu_b0[j], l = ls_b0[j], e = eps_b0[j];
        float4 r;
        r.x = fmaf(expf(l.x), e.x, m.x);
        r.y = fmaf(expf(l.y), e.y, m.y);
        r.z = fmaf(expf(l.z), e.z, m.z);
        r.w = fmaf(expf(l.w), e.w, m.w);
        reinterpret_cast<float4*>(g_bias)[j] = r;
    }
}

// per-layer weight gen (fp16); off4 = float4 offset into g_w_f
__global__ void gen_w4_kernel(const float4* __restrict__ mu,
                              const float4* __restrict__ ls,
                              const float4* __restrict__ eps,
                              int off4) {
    int i = blockIdx.x * blockDim.x + threadIdx.x;
    if (i >= N4W) return;
    float4 m = mu[i], l = ls[i], e = eps[i];
    reinterpret_cast<uint2*>(g_w_f)[off4 + i] = pack4h(
        fmaf(expf(l.x), e.x, m.x), fmaf(expf(l.y), e.y, m.y),
        fmaf(expf(l.z), e.z, m.z), fmaf(expf(l.w), e.w, m.w));
}

// small gens merged: biases 1..3 (f32), head weights (f16), head biases (f32)
__global__ void gen_rest_kernel(const float* __restrict__ mu_b,  const float* __restrict__ ls_b,  const float* __restrict__ eps_b,
                                const float* __restrict__ mu_hw, const float* __restrict__ ls_hw, const float* __restrict__ eps_hw,
                                const float* __restrict__ mu_hb, const float* __restrict__ ls_hb, const float* __restrict__ eps_hb) {
    const int n1 = NEX * HID;
    const int n2 = NT * OUTD * HID;
    const int n3 = NT * OUTD;
    int i = blockIdx.x * blockDim.x + threadIdx.x;
    if (i < n1) {
        g_bias[HID + i] = fmaf(expf(ls_b[i]), eps_b[i], mu_b[i]);
    } else if (i < n1 + n2) {
        int j = i - n1;
        g_hw[j] = __float2half_rn(fmaf(expf(ls_hw[j]), eps_hw[j], mu_hw[j]));
    } else if (i < n1 + n2 + n3) {
        int j = i - n1 - n2;
        g_hb[j] = fmaf(expf(ls_hb[j]), eps_hb[j], mu_hb[j]);
    }
}

// ---------------- HMMA primitives ----------------
__device__ __forceinline__ void ldsm4(uint32_t d[4], uint32_t addr) {
    asm volatile("ldmatrix.sync.aligned.m8n8.x4.shared.b16 {%0,%1,%2,%3}, [%4];"
                 : "=r"(d[0]), "=r"(d[1]), "=r"(d[2]), "=r"(d[3]) : "r"(addr));
}

__device__ __forceinline__ void mma_f16(float c[4], const uint32_t a[4], const uint32_t b[2]) {
    asm volatile("mma.sync.aligned.m16n8k16.row.col.f32.f16.f16.f32 "
                 "{%0,%1,%2,%3}, {%4,%5,%6,%7}, {%8,%9}, {%0,%1,%2,%3};"
                 : "+f"(c[0]), "+f"(c[1]), "+f"(c[2]), "+f"(c[3])
                 : "r"(a[0]), "r"(a[1]), "r"(a[2]), "r"(a[3]), "r"(b[0]), "r"(b[1]));
}

__device__ __forceinline__ void cp16(uint32_t dst, const void* src) {
    asm volatile("cp.async.cg.shared.global [%0], [%1], 16;" :: "r"(dst), "l"(src) : "memory");
}

// load one BK=64 chunk: A (128x64 fp16) + B (64x64 fp16); 12 cp16/thread
__device__ __forceinline__ void load_chunk(
    uint32_t sb,
    const __half* __restrict__ A, const __half* __restrict__ W,
    int K, int m0, int n0, int kc, int tid)
{
#pragma unroll
    for (int j = 0; j < 8; j++) {        // A: 128 rows x 8 16B-chunks = 1024 lines
        int idx = tid + j * GTHREADS;
        int row = idx >> 3, ch = idx & 7;
        uint32_t dst = sb + SA + (uint32_t)(row * PADB + ch * 16);
        size_t g = (size_t)(m0 + row) * K + kc + ch * 8;
        cp16(dst, A + g);
    }
#pragma unroll
    for (int j = 0; j < 4; j++) {        // B: 64 rows x 8 chunks = 512 lines
        int idx = tid + j * GTHREADS;
        int row = idx >> 3, ch = idx & 7;
        uint32_t dst = sb + SB + (uint32_t)(row * PADB + ch * 16);
        size_t g = (size_t)(n0 + row) * K + kc + ch * 8;
        cp16(dst, W + g);
    }
}

// ---------------- fp16 GEMM: C = relu(A*W^T + bias) ----------------
__global__ __launch_bounds__(GTHREADS, 4) void gemm_kernel(int layer, int a_sel, int out_sel) {
    const __half *A, *W;
    const float* bias;
    int K;
    if (layer == 0) {
        A = g_x_f; W = g_w0_f;
        bias = g_bias; K = IN_DIM;
    } else {
        A = g_h[a_sel];
        W = g_w_f + (size_t)(layer - 1) * HID * HID;
        bias = g_bias + layer * HID; K = HID;
    }
    __half* C = g_h[out_sel];
    const int NC = K / BK;

    extern __shared__ __align__(128) uint8_t dyn[];
    const uint32_t sbase = (uint32_t)__cvta_generic_to_shared(dyn);

    const int tid  = threadIdx.x;
    const int warp = tid >> 5;
    const int lane = tid & 31;
    const int m0 = blockIdx.y * BM;
    const int n0 = blockIdx.x * BN;
    const int wm0 = (warp & 1) * 64;    // 2 warps along M, tile 64
    const int wn0 = (warp >> 1) * 32;   // 2 warps along N, tile 32

    float acc[4][4][4];
#pragma unroll
    for (int mt = 0; mt < 4; mt++)
#pragma unroll
        for (int nt = 0; nt < 4; nt++)
#pragma unroll
            for (int i = 0; i < 4; i++) acc[mt][nt][i] = 0.f;

    // prologue: chunk 0 -> stage 0
    load_chunk(sbase, A, W, K, m0, n0, 0, tid);
    asm volatile("cp.async.commit_group;" ::: "memory");

    for (int i = 0; i < NC; i++) {
        asm volatile("cp.async.wait_group 0;" ::: "memory");
        __syncthreads();
        // prefetch AFTER sync: all threads done reading the stage being overwritten
        if (i + 1 < NC) {
            load_chunk(sbase + (uint32_t)((i + 1) & 1) * STAGE,
                       A, W, K, m0, n0, (i + 1) * BK, tid);
            asm volatile("cp.async.commit_group;" ::: "memory");
        }

        const uint32_t sb = sbase + (uint32_t)(i & 1) * STAGE;
#pragma unroll
        for (int kk = 0; kk < BK; kk += 16) {
            uint32_t af[4][4];
            const int rA  = lane & 15;
            const int chA = (kk >> 3) + (lane >> 4);
#pragma unroll
            for (int mt = 0; mt < 4; mt++) {
                uint32_t off = (uint32_t)((wm0 + mt * 16 + rA) * PADB + chA * 16);
                ldsm4(af[mt], sb + SA + off);
            }
            const int rB  = (lane & 7) + ((lane >> 4) << 3);
            const int chB = (kk >> 3) + ((lane >> 3) & 1);
#pragma unroll
            for (int np = 0; np < 2; np++) {
                uint32_t off = (uint32_t)((wn0 + np * 16 + rB) * PADB + chB * 16);
                uint32_t bf[4];
                ldsm4(bf, sb + SB + off);
#pragma unroll
                for (int sub = 0; sub < 2; sub++) {
                    const int nt = np * 2 + sub;
                    const uint32_t b2[2] = { bf[sub * 2], bf[sub * 2 + 1] };
#pragma unroll
                    for (int mt = 0; mt < 4; mt++) {
                        mma_f16(acc[mt][nt], af[mt], b2);
                    }
                }
            }
        }
    }

    // ---- epilogue: bias + relu -> fp16 ----
    const int gid  = lane >> 2;
    const int tid4 = lane & 3;
#pragma unroll
    for (int nt = 0; nt < 4; nt++) {
        const int col = n0 + wn0 + nt * 8 + tid4 * 2;
        const float bz0 = bias[col];
        const float bz1 = bias[col + 1];
#pragma unroll
        for (int mt = 0; mt < 4; mt++) {
            const int rowm = m0 + wm0 + mt * 16 + gid;
            const float* a = acc[mt][nt];
            {
                float v0 = fmaxf(a[0] + bz0, 0.f);
                float v1 = fmaxf(a[1] + bz1, 0.f);
                *reinterpret_cast<__half2*>(C + (size_t)rowm * HID + col) =
                    __halves2half2(__float2half_rn(v0), __float2half_rn(v1));
            }
            {
                float v0 = fmaxf(a[2] + bz0, 0.f);
                float v1 = fmaxf(a[3] + bz1, 0.f);
                *reinterpret_cast<__half2*>(C + (size_t)(rowm + 8) * HID + col) =
                    __halves2half2(__float2half_rn(v0), __float2half_rn(v1));
            }
        }
    }
}

// ---------------- task-gathered multihead (half2-vectorized) ----------------
__global__ __launch_bounds__(128) void head_kernel(int h_sel,
                                                   const int* __restrict__ task32,
                                                   float* __restrict__ out) {
    const int b = blockIdx.x;
    int t = g_task_is64 ? task32[2 * b] : task32[b];
    t = min(max(t, 0), NT - 1);

    const __half2* h2  = reinterpret_cast<const __half2*>(g_h[h_sel] + (size_t)b * HID);
    const __half2* hw2 = reinterpret_cast<const __half2*>(g_hw + (size_t)t * OUTD * HID);

    float acc[OUTD];
#pragma unroll
    for (int o = 0; o < OUTD; o++) acc[o] = 0.f;

    for (int k2 = threadIdx.x; k2 < HID / 2; k2 += blockDim.x) {
        float2 hv = __half22float2(h2[k2]);
#pragma unroll
        for (int o = 0; o < OUTD; o++) {
            float2 wv = __half22float2(hw2[o * (HID / 2) + k2]);
            acc[o] = fmaf(hv.x, wv.x, fmaf(hv.y, wv.y, acc[o]));
        }
    }

    const int warp = threadIdx.x >> 5;
    const int lane = threadIdx.x & 31;
    __shared__ float red[4][OUTD];
#pragma unroll
    for (int o = 0; o < OUTD; o++) {
        float v = acc[o];
#pragma unroll
        for (int s = 16; s > 0; s >>= 1) v += __shfl_xor_sync(0xffffffffu, v, s);
        if (lane == 0) red[warp][o] = v;
    }
    __syncthreads();
    if (threadIdx.x < OUTD) {
        float s = red[0][threadIdx.x] + red[1][threadIdx.x] +
                  red[2][threadIdx.x] + red[3][threadIdx.x] +
                  g_hb[t * OUTD + threadIdx.x];
        out[(size_t)b * OUTD + threadIdx.x] = s;
    }
}

// ---------------- launch ----------------
extern "C" void kernel_launch(void* const* d_in, const int* in_sizes, int n_in,
                              void* d_out, int out_size) {
    (void)in_sizes; (void)n_in; (void)out_size;
    const float* x      = (const float*)d_in[0];
    const float* mu_w0  = (const float*)d_in[1];
    const float* ls_w0  = (const float*)d_in[2];
    const float* mu_b0  = (const float*)d_in[3];
    const float* ls_b0  = (const float*)d_in[4];
    const float* mu_w   = (const float*)d_in[5];
    const float* ls_w   = (const float*)d_in[6];
    const float* mu_b   = (const float*)d_in[7];
    const float* ls_b   = (const float*)d_in[8];
    const float* mu_hw  = (const float*)d_in[9];
    const float* ls_hw  = (const float*)d_in[10];
    const float* mu_hb  = (const float*)d_in[11];
    const float* ls_hb  = (const float*)d_in[12];
    const float* eps_w0 = (const float*)d_in[13];
    const float* eps_b0 = (const float*)d_in[14];
    const float* eps_w  = (const float*)d_in[15];
    const float* eps_b  = (const float*)d_in[16];
    const float* eps_hw = (const float*)d_in[17];
    const float* eps_hb = (const float*)d_in[18];
    const int* task32   = (const int*)d_in[19];
    float* out = (float*)d_out;

    cudaFuncSetAttribute(gemm_kernel,
                         cudaFuncAttributeMaxDynamicSharedMemorySize, DYN_SMEM);

    const int nblk_w = (N4W + 255) / 256;

    // ---- fork: side chain with per-layer completion events ----
    cudaEventRecord(g_ev_fork, 0);
    cudaStreamWaitEvent(g_side_stream, g_ev_fork, 0);

    detect_task_kernel<<<1, 256, 0, g_side_stream>>>(task32);
    {
        int nr = NEX * HID + NT * OUTD * HID + NT * OUTD;
        gen_rest_kernel<<<(nr + 255) / 256, 256, 0, g_side_stream>>>(
            mu_b, ls_b, eps_b, mu_hw, ls_hw, eps_hw, mu_hb, ls_hb, eps_hb);
    }
    gen_w4_kernel<<<nblk_w, 256, 0, g_side_stream>>>(
        (const float4*)mu_w, (const float4*)ls_w, (const float4*)eps_w, 0);
    cudaEventRecord(g_ev_j1, g_side_stream);
    gen_w4_kernel<<<nblk_w, 256, 0, g_side_stream>>>(
        (const float4*)(mu_w)  + N4W, (const float4*)(ls_w)  + N4W,
        (const float4*)(eps_w) + N4W, N4W);
    cudaEventRecord(g_ev_j2, g_side_stream);
    gen_w4_kernel<<<nblk_w, 256, 0, g_side_stream>>>(
        (const float4*)(mu_w)  + 2 * N4W, (const float4*)(ls_w)  + 2 * N4W,
        (const float4*)(eps_w) + 2 * N4W, 2 * N4W);
    cudaEventRecord(g_ev_j3, g_side_stream);

    // ---- main chain ----
    {
        int ntot = N4X + N4W0 + N4B0;
        fused_pre_kernel<<<(ntot + 255) / 256, 256>>>(
            (const float4*)x,
            (const float4*)mu_w0, (const float4*)ls_w0, (const float4*)eps_w0,
            (const float4*)mu_b0, (const float4*)ls_b0, (const float4*)eps_b0);
    }

    dim3 grid(HID / BN, BATCH / BM);   // (32, 32) = 1024 CTAs
    gemm_kernel<<<grid, GTHREADS, DYN_SMEM>>>(0, 0, 0);

    cudaStreamWaitEvent(0, g_ev_j1, 0);
    gemm_kernel<<<grid, GTHREADS, DYN_SMEM>>>(1, 0, 1);
    cudaStreamWaitEvent(0, g_ev_j2, 0);
    gemm_kernel<<<grid, GTHREADS, DYN_SMEM>>>(2, 1, 0);
    cudaStreamWaitEvent(0, g_ev_j3, 0);
    gemm_kernel<<<grid, GTHREADS, DYN_SMEM>>>(3, 0, 1);
    head_kernel<<<BATCH, 128>>>(1, task32, out);
}